// round 1
// baseline (speedup 1.0000x reference)
#include <cuda_runtime.h>

// Problem constants
#define B_SZ   4096
#define F_SZ   100
#define H_SZ   128
#define H2_SZ  64
#define T_SZ   2

// Tiling
#define TB      64      // batch rows per CTA tile
#define FG      10      // features per CTA
#define THREADS 256
#define AP      (H_SZ + 4)   // padded activation row stride (floats)

// Precomputed collapsed head: wv[f,t,h] = sum_m Wh1[f,t,h,m]*Wh2[f,t,m]
__device__ float g_wv[F_SZ * T_SZ * H_SZ];
__device__ float g_c[F_SZ * T_SZ];

// ---------------- packed f32x2 helpers (sm_103a) ----------------
__device__ __forceinline__ unsigned long long pack_dup(float v) {
    unsigned long long r;
    asm("mov.b64 %0, {%1, %1};" : "=l"(r) : "f"(v));
    return r;
}
__device__ __forceinline__ unsigned long long fma2(unsigned long long a,
                                                   unsigned long long b,
                                                   unsigned long long c) {
    unsigned long long d;
    asm("fma.rn.f32x2 %0, %1, %2, %3;" : "=l"(d) : "l"(a), "l"(b), "l"(c));
    return d;
}
__device__ __forceinline__ float2 unpack2(unsigned long long v) {
    float2 f;
    asm("mov.b64 {%0, %1}, %2;" : "=f"(f.x), "=f"(f.y) : "l"(v));
    return f;
}
__device__ __forceinline__ float elu_f(float v) {
    // alpha=1 ELU; __expf error ~1e-6 rel, abs error near 0 is ~1e-7 -> negligible
    return v > 0.0f ? v : (__expf(v) - 1.0f);
}

// ---------------- zero output ----------------
__global__ void nam_zero(float* __restrict__ out, int n) {
    int i = blockIdx.x * blockDim.x + threadIdx.x;
    if (i < n) out[i] = 0.0f;
}

// ---------------- head collapse precompute ----------------
// grid = F*T blocks of H threads
__global__ void nam_precompute(const float* __restrict__ Wh1,
                               const float* __restrict__ bh1,
                               const float* __restrict__ Wh2,
                               const float* __restrict__ bh2) {
    int ft = blockIdx.x;          // f*T + t
    int h  = threadIdx.x;         // 0..127
    __shared__ float s2[H2_SZ];
    if (h < H2_SZ) s2[h] = Wh2[ft * H2_SZ + h];
    __syncthreads();
    const float* wp = Wh1 + ((long)ft * H_SZ + h) * H2_SZ;
    float s = 0.0f;
#pragma unroll 8
    for (int m = 0; m < H2_SZ; m++) s += wp[m] * s2[m];
    g_wv[ft * H_SZ + h] = s;
    if (h == 0) {
        float cc = bh2[ft];
        const float* bp = bh1 + ft * H2_SZ;
        for (int m = 0; m < H2_SZ; m++) cc += bp[m] * s2[m];
        g_c[ft] = cc;
    }
}

// ---------------- fused main kernel ----------------
__device__ __forceinline__ void load_w_full(float* __restrict__ sW,
                                            const float* __restrict__ g, int tid) {
    const float4* g4 = (const float4*)g;
    float4* s4 = (float4*)sW;
#pragma unroll
    for (int i = tid; i < H_SZ * H_SZ / 4; i += THREADS) s4[i] = g4[i];
}

// GEMM over k: acc[r][cp] accumulates rows r0..r0+3, packed col pairs c0..c0+7
__device__ __forceinline__ void gemm_tile(const float* __restrict__ sIn,
                                          const float* __restrict__ sW,
                                          int r0, int c0,
                                          unsigned long long acc[4][4]) {
#pragma unroll
    for (int r = 0; r < 4; r++)
#pragma unroll
        for (int c = 0; c < 4; c++) acc[r][c] = 0ull;

    const float* a0p = sIn + (r0 + 0) * AP;
    const float* a1p = sIn + (r0 + 1) * AP;
    const float* a2p = sIn + (r0 + 2) * AP;
    const float* a3p = sIn + (r0 + 3) * AP;

#pragma unroll 4
    for (int k = 0; k < H_SZ; k++) {
        unsigned long long a0 = pack_dup(a0p[k]);
        unsigned long long a1 = pack_dup(a1p[k]);
        unsigned long long a2 = pack_dup(a2p[k]);
        unsigned long long a3 = pack_dup(a3p[k]);
        const ulonglong2* wp = (const ulonglong2*)(sW + k * H_SZ + c0);
        ulonglong2 wA = wp[0];   // cols c0..c0+3
        ulonglong2 wB = wp[1];   // cols c0+4..c0+7
        acc[0][0] = fma2(a0, wA.x, acc[0][0]);
        acc[0][1] = fma2(a0, wA.y, acc[0][1]);
        acc[0][2] = fma2(a0, wB.x, acc[0][2]);
        acc[0][3] = fma2(a0, wB.y, acc[0][3]);
        acc[1][0] = fma2(a1, wA.x, acc[1][0]);
        acc[1][1] = fma2(a1, wA.y, acc[1][1]);
        acc[1][2] = fma2(a1, wB.x, acc[1][2]);
        acc[1][3] = fma2(a1, wB.y, acc[1][3]);
        acc[2][0] = fma2(a2, wA.x, acc[2][0]);
        acc[2][1] = fma2(a2, wA.y, acc[2][1]);
        acc[2][2] = fma2(a2, wB.x, acc[2][2]);
        acc[2][3] = fma2(a2, wB.y, acc[2][3]);
        acc[3][0] = fma2(a3, wA.x, acc[3][0]);
        acc[3][1] = fma2(a3, wA.y, acc[3][1]);
        acc[3][2] = fma2(a3, wB.x, acc[3][2]);
        acc[3][3] = fma2(a3, wB.y, acc[3][3]);
    }
}

__global__ void __launch_bounds__(THREADS, 1)
nam_main(const float* __restrict__ x, const int* __restrict__ a,
         const float* __restrict__ W1, const float* __restrict__ b1,
         const float* __restrict__ W2, const float* __restrict__ b2,
         const float* __restrict__ W3, const float* __restrict__ b3,
         const float* __restrict__ W4, const float* __restrict__ b4,
         float* __restrict__ out) {
    extern __shared__ float smem[];
    float* sA0   = smem;                       // TB*AP
    float* sA1   = sA0 + TB * AP;              // TB*AP
    float* sW    = sA1 + TB * AP;              // H*H
    float* sbias = sW + H_SZ * H_SZ;           // H
    float* swv   = sbias + H_SZ;               // T*H
    float* sc    = swv + T_SZ * H_SZ;          // T
    float* sx    = sc + T_SZ;                  // TB
    int*   sa    = (int*)(sx + TB);            // TB

    const int tid = threadIdx.x;
    const int tx = tid & 15;       // column group (8 cols)
    const int ty = tid >> 4;       // row group (4 rows)
    const int r0 = ty * 4;
    const int c0 = tx * 8;
    const int b0 = blockIdx.x * TB;
    const int fbase = blockIdx.y * FG;

    if (tid < TB) sa[tid] = a[b0 + tid];

    float bbsum[4][8];
#pragma unroll
    for (int r = 0; r < 4; r++)
#pragma unroll
        for (int c = 0; c < 8; c++) bbsum[r][c] = 0.0f;
    float yacc[4] = {0.f, 0.f, 0.f, 0.f};

    for (int ff = 0; ff < FG; ff++) {
        const int f = fbase + ff;
        __syncthreads();  // protect smem reuse from previous iteration

        // per-feature small loads: x column, W1 row, b1 row, wv, c
        if (tid < TB)   sx[tid] = x[(b0 + tid) * F_SZ + f];
        if (tid < H_SZ) { sW[tid] = W1[f * H_SZ + tid]; sbias[tid] = b1[f * H_SZ + tid]; }
        swv[tid] = g_wv[f * T_SZ * H_SZ + tid];     // 256 values exactly
        if (tid < T_SZ) sc[tid] = g_c[f * T_SZ + tid];
        __syncthreads();

        // ---- layer 1 (elementwise): sA0 = elu(x*W1 + b1) ----
#pragma unroll
        for (int idx = tid; idx < TB * H_SZ; idx += THREADS) {
            int i = idx >> 7, j = idx & 127;
            sA0[i * AP + j] = elu_f(sx[i] * sW[j] + sbias[j]);
        }
        __syncthreads();  // layer1 done reading sW(W1) and writing sA0

        unsigned long long acc[4][4];

        // ---- layer 2: sA1 = elu(sA0 @ W2 + b2) ----
        load_w_full(sW, W2 + (long)f * H_SZ * H_SZ, tid);
        if (tid < H_SZ) sbias[tid] = b2[f * H_SZ + tid];
        __syncthreads();
        gemm_tile(sA0, sW, r0, c0, acc);
        {
            float bias8[8];
            *(float4*)&bias8[0] = *(const float4*)&sbias[c0];
            *(float4*)&bias8[4] = *(const float4*)&sbias[c0 + 4];
#pragma unroll
            for (int r = 0; r < 4; r++) {
                float o[8];
#pragma unroll
                for (int c = 0; c < 4; c++) {
                    float2 v = unpack2(acc[r][c]);
                    o[2 * c]     = elu_f(v.x + bias8[2 * c]);
                    o[2 * c + 1] = elu_f(v.y + bias8[2 * c + 1]);
                }
                *(float4*)&sA1[(r0 + r) * AP + c0]     = *(float4*)&o[0];
                *(float4*)&sA1[(r0 + r) * AP + c0 + 4] = *(float4*)&o[4];
            }
        }
        __syncthreads();

        // ---- layer 3: sA0 = elu(sA1 @ W3 + b3) ----
        load_w_full(sW, W3 + (long)f * H_SZ * H_SZ, tid);
        if (tid < H_SZ) sbias[tid] = b3[f * H_SZ + tid];
        __syncthreads();
        gemm_tile(sA1, sW, r0, c0, acc);
        {
            float bias8[8];
            *(float4*)&bias8[0] = *(const float4*)&sbias[c0];
            *(float4*)&bias8[4] = *(const float4*)&sbias[c0 + 4];
#pragma unroll
            for (int r = 0; r < 4; r++) {
                float o[8];
#pragma unroll
                for (int c = 0; c < 4; c++) {
                    float2 v = unpack2(acc[r][c]);
                    o[2 * c]     = elu_f(v.x + bias8[2 * c]);
                    o[2 * c + 1] = elu_f(v.y + bias8[2 * c + 1]);
                }
                *(float4*)&sA0[(r0 + r) * AP + c0]     = *(float4*)&o[0];
                *(float4*)&sA0[(r0 + r) * AP + c0 + 4] = *(float4*)&o[4];
            }
        }
        __syncthreads();

        // ---- layer 4: bb = sA0 @ W4 + b4 (no elu), stays in registers ----
        load_w_full(sW, W4 + (long)f * H_SZ * H_SZ, tid);
        if (tid < H_SZ) sbias[tid] = b4[f * H_SZ + tid];
        __syncthreads();
        gemm_tile(sA0, sW, r0, c0, acc);
        {
            float bias8[8];
            *(float4*)&bias8[0] = *(const float4*)&sbias[c0];
            *(float4*)&bias8[4] = *(const float4*)&sbias[c0 + 4];
#pragma unroll
            for (int r = 0; r < 4; r++) {
                float bb8[8];
#pragma unroll
                for (int c = 0; c < 4; c++) {
                    float2 v = unpack2(acc[r][c]);
                    bb8[2 * c]     = v.x + bias8[2 * c];
                    bb8[2 * c + 1] = v.y + bias8[2 * c + 1];
                }
                const int row = r0 + r;
                const int t = sa[row];
                const float* wvp = swv + t * H_SZ + c0;
                float p = 0.0f;
#pragma unroll
                for (int c = 0; c < 8; c++) {
                    bbsum[r][c] += bb8[c];
                    p += bb8[c] * wvp[c];
                }
                // reduce p across the 16 column-threads (lane%16 == tx)
                p += __shfl_xor_sync(0xffffffffu, p, 1, 16);
                p += __shfl_xor_sync(0xffffffffu, p, 2, 16);
                p += __shfl_xor_sync(0xffffffffu, p, 4, 16);
                p += __shfl_xor_sync(0xffffffffu, p, 8, 16);
                if (tx == 0) yacc[r] += p + sc[t];
            }
        }
        // gemm reads of sW/sA0 complete before next-iteration loop-top sync
    }

    // ---- final cross-feature-group reduction via fp32 atomics ----
#pragma unroll
    for (int r = 0; r < 4; r++) {
        const int row = b0 + r0 + r;
#pragma unroll
        for (int c = 0; c < 8; c++)
            atomicAdd(&out[row * H_SZ + c0 + c], bbsum[r][c]);
    }
    if (tx == 0) {
#pragma unroll
        for (int r = 0; r < 4; r++)
            atomicAdd(&out[B_SZ * H_SZ + b0 + r0 + r], yacc[r]);
    }
}

// ---------------- launch ----------------
extern "C" void kernel_launch(void* const* d_in, const int* in_sizes, int n_in,
                              void* d_out, int out_size) {
    const float* x   = (const float*)d_in[0];
    const int*   a   = (const int*)d_in[1];
    const float* W1  = (const float*)d_in[2];
    const float* b1  = (const float*)d_in[3];
    const float* W2  = (const float*)d_in[4];
    const float* b2  = (const float*)d_in[5];
    const float* W3  = (const float*)d_in[6];
    const float* b3  = (const float*)d_in[7];
    const float* W4  = (const float*)d_in[8];
    const float* b4  = (const float*)d_in[9];
    const float* Wh1 = (const float*)d_in[10];
    const float* bh1 = (const float*)d_in[11];
    const float* Wh2 = (const float*)d_in[12];
    const float* bh2 = (const float*)d_in[13];
    float* out = (float*)d_out;

    const int smem_bytes =
        (2 * TB * AP + H_SZ * H_SZ + H_SZ + T_SZ * H_SZ + T_SZ + TB) * 4 + TB * 4;
    cudaFuncSetAttribute(nam_main, cudaFuncAttributeMaxDynamicSharedMemorySize,
                         smem_bytes);

    nam_zero<<<(out_size + 255) / 256, 256>>>(out, out_size);
    nam_precompute<<<F_SZ * T_SZ, H_SZ>>>(Wh1, bh1, Wh2, bh2);

    dim3 grid(B_SZ / TB, F_SZ / FG);
    nam_main<<<grid, THREADS, smem_bytes>>>(x, a, W1, b1, W2, b2, W3, b3, W4, b4, out);
}

// round 2
// speedup vs baseline: 1.1409x; 1.1409x over previous
#include <cuda_runtime.h>
#include <cstdint>

// Problem constants
#define B_SZ   4096
#define F_SZ   100
#define H_SZ   128
#define H2_SZ  64
#define T_SZ   2

// Tiling
#define TB      64      // batch rows per CTA tile
#define FG      5       // features per CTA
#define THREADS 256
#define AP      (H_SZ + 4)   // padded activation row stride (floats)

// Precomputed collapsed head: wv[f,t,h] = sum_m Wh1[f,t,h,m]*Wh2[f,t,m]
__device__ float g_wv[F_SZ * T_SZ * H_SZ];
__device__ float g_c[F_SZ * T_SZ];

// ---------------- packed f32x2 helpers (sm_103a) ----------------
__device__ __forceinline__ unsigned long long pack_dup(float v) {
    unsigned long long r;
    asm("mov.b64 %0, {%1, %1};" : "=l"(r) : "f"(v));
    return r;
}
__device__ __forceinline__ unsigned long long fma2(unsigned long long a,
                                                   unsigned long long b,
                                                   unsigned long long c) {
    unsigned long long d;
    asm("fma.rn.f32x2 %0, %1, %2, %3;" : "=l"(d) : "l"(a), "l"(b), "l"(c));
    return d;
}
__device__ __forceinline__ float2 unpack2(unsigned long long v) {
    float2 f;
    asm("mov.b64 {%0, %1}, %2;" : "=f"(f.x), "=f"(f.y) : "l"(v));
    return f;
}
__device__ __forceinline__ float elu_f(float v) {
    return v > 0.0f ? v : (__expf(v) - 1.0f);
}

// ---------------- cp.async helpers ----------------
__device__ __forceinline__ void cp16(uint32_t saddr, const float* g) {
    asm volatile("cp.async.cg.shared.global [%0], [%1], 16;\n"
                 :: "r"(saddr), "l"(g));
}
__device__ __forceinline__ void cp_commit() {
    asm volatile("cp.async.commit_group;\n" ::: "memory");
}
__device__ __forceinline__ void cp_wait0() {
    asm volatile("cp.async.wait_group 0;\n" ::: "memory");
}
// async copy one 64KB weight matrix (H*H floats), 256 threads x 16 chunks x 16B
__device__ __forceinline__ void issue_w(float* sdst, const float* gsrc, int tid) {
    uint32_t base = (uint32_t)__cvta_generic_to_shared(sdst);
#pragma unroll
    for (int i = 0; i < 16; i++) {
        int e = (tid + i * THREADS) * 4;            // float index
        cp16(base + e * 4, gsrc + e);
    }
    cp_commit();
}

// ---------------- combined setup: zero output + head collapse ----------------
__global__ void nam_setup(float* __restrict__ out, int n_out,
                          const float* __restrict__ Wh1,
                          const float* __restrict__ bh1,
                          const float* __restrict__ Wh2,
                          const float* __restrict__ bh2) {
    const int blk = blockIdx.x;
    const int tid = threadIdx.x;
    if (blk < F_SZ * T_SZ) {
        // precompute part (first 128 threads do the work)
        __shared__ float s2[H2_SZ];
        if (tid < H2_SZ) s2[tid] = Wh2[blk * H2_SZ + tid];
        __syncthreads();
        if (tid < H_SZ) {
            const float* wp = Wh1 + ((long)blk * H_SZ + tid) * H2_SZ;
            float s = 0.0f;
#pragma unroll 8
            for (int m = 0; m < H2_SZ; m++) s += wp[m] * s2[m];
            g_wv[blk * H_SZ + tid] = s;
            if (tid == 0) {
                float cc = bh2[blk];
                const float* bp = bh1 + blk * H2_SZ;
                for (int m = 0; m < H2_SZ; m++) cc += bp[m] * s2[m];
                g_c[blk] = cc;
            }
        }
    } else {
        int i = (blk - F_SZ * T_SZ) * THREADS + tid;
        if (i < n_out) out[i] = 0.0f;
    }
}

// ---------------- GEMM tile: rows r0..r0+3, packed col pairs c0..c0+7 ----------
__device__ __forceinline__ void gemm_tile(const float* __restrict__ sIn,
                                          const float* __restrict__ sW,
                                          int r0, int c0,
                                          unsigned long long acc[4][4]) {
#pragma unroll
    for (int r = 0; r < 4; r++)
#pragma unroll
        for (int c = 0; c < 4; c++) acc[r][c] = 0ull;

    const float* a0p = sIn + (r0 + 0) * AP;
    const float* a1p = sIn + (r0 + 1) * AP;
    const float* a2p = sIn + (r0 + 2) * AP;
    const float* a3p = sIn + (r0 + 3) * AP;

    for (int k = 0; k < H_SZ; k += 4) {
        float a0v[4], a1v[4], a2v[4], a3v[4];
        *(float4*)a0v = *(const float4*)(a0p + k);
        *(float4*)a1v = *(const float4*)(a1p + k);
        *(float4*)a2v = *(const float4*)(a2p + k);
        *(float4*)a3v = *(const float4*)(a3p + k);
#pragma unroll
        for (int kk = 0; kk < 4; kk++) {
            unsigned long long p0 = pack_dup(a0v[kk]);
            unsigned long long p1 = pack_dup(a1v[kk]);
            unsigned long long p2 = pack_dup(a2v[kk]);
            unsigned long long p3 = pack_dup(a3v[kk]);
            const ulonglong2* wp = (const ulonglong2*)(sW + (k + kk) * H_SZ + c0);
            ulonglong2 wA = wp[0];   // cols c0..c0+3
            ulonglong2 wB = wp[1];   // cols c0+4..c0+7
            acc[0][0] = fma2(p0, wA.x, acc[0][0]);
            acc[0][1] = fma2(p0, wA.y, acc[0][1]);
            acc[0][2] = fma2(p0, wB.x, acc[0][2]);
            acc[0][3] = fma2(p0, wB.y, acc[0][3]);
            acc[1][0] = fma2(p1, wA.x, acc[1][0]);
            acc[1][1] = fma2(p1, wA.y, acc[1][1]);
            acc[1][2] = fma2(p1, wB.x, acc[1][2]);
            acc[1][3] = fma2(p1, wB.y, acc[1][3]);
            acc[2][0] = fma2(p2, wA.x, acc[2][0]);
            acc[2][1] = fma2(p2, wA.y, acc[2][1]);
            acc[2][2] = fma2(p2, wB.x, acc[2][2]);
            acc[2][3] = fma2(p2, wB.y, acc[2][3]);
            acc[3][0] = fma2(p3, wA.x, acc[3][0]);
            acc[3][1] = fma2(p3, wA.y, acc[3][1]);
            acc[3][2] = fma2(p3, wB.x, acc[3][2]);
            acc[3][3] = fma2(p3, wB.y, acc[3][3]);
        }
    }
}

// epilogue with ELU -> smem dest
__device__ __forceinline__ void epi_elu(unsigned long long acc[4][4],
                                        const float* __restrict__ sb,
                                        float* __restrict__ sDst,
                                        int r0, int c0) {
    float bias8[8];
    *(float4*)&bias8[0] = *(const float4*)&sb[c0];
    *(float4*)&bias8[4] = *(const float4*)&sb[c0 + 4];
#pragma unroll
    for (int r = 0; r < 4; r++) {
        float o[8];
#pragma unroll
        for (int c = 0; c < 4; c++) {
            float2 v = unpack2(acc[r][c]);
            o[2 * c]     = elu_f(v.x + bias8[2 * c]);
            o[2 * c + 1] = elu_f(v.y + bias8[2 * c + 1]);
        }
        *(float4*)&sDst[(r0 + r) * AP + c0]     = *(float4*)&o[0];
        *(float4*)&sDst[(r0 + r) * AP + c0 + 4] = *(float4*)&o[4];
    }
}

// ---------------- fused main kernel ----------------
__global__ void __launch_bounds__(THREADS, 1)
nam_main(const float* __restrict__ x, const int* __restrict__ a,
         const float* __restrict__ W1, const float* __restrict__ b1,
         const float* __restrict__ W2, const float* __restrict__ b2,
         const float* __restrict__ W3, const float* __restrict__ b3,
         const float* __restrict__ W4, const float* __restrict__ b4,
         float* __restrict__ out) {
    extern __shared__ float smem[];
    float* sA0  = smem;                        // TB*AP
    float* sA1  = sA0 + TB * AP;               // TB*AP
    float* sWb0 = sA1 + TB * AP;               // H*H
    float* sWb1 = sWb0 + H_SZ * H_SZ;          // H*H
    float* sw1  = sWb1 + H_SZ * H_SZ;          // H
    float* sb1v = sw1 + H_SZ;                  // H
    float* sb2v = sb1v + H_SZ;                 // H
    float* sb3v = sb2v + H_SZ;                 // H
    float* sb4v = sb3v + H_SZ;                 // H
    float* swv  = sb4v + H_SZ;                 // T*H
    float* sc   = swv + T_SZ * H_SZ;           // T
    float* sx   = sc + T_SZ;                   // TB
    int*   sa   = (int*)(sx + TB);             // TB

    const int tid = threadIdx.x;
    const int tx = tid & 15;       // column group (8 cols)
    const int ty = tid >> 4;       // row group (4 rows)
    const int r0 = ty * 4;
    const int c0 = tx * 8;
    const int b0 = blockIdx.x * TB;
    const int fbase = blockIdx.y * FG;

    if (tid < TB) sa[tid] = a[b0 + tid];

    float bbsum[4][8];
#pragma unroll
    for (int r = 0; r < 4; r++)
#pragma unroll
        for (int c = 0; c < 8; c++) bbsum[r][c] = 0.0f;
    float yacc[4] = {0.f, 0.f, 0.f, 0.f};

    // prologue: async-load W2 of first feature
    float* Wcur = sWb0;
    float* Wnxt = sWb1;
    issue_w(Wcur, W2 + (long)fbase * H_SZ * H_SZ, tid);

    for (int ff = 0; ff < FG; ff++) {
        const int f = fbase + ff;
        __syncthreads();  // protect small-load buffers + prev-feature reads

        // per-feature small loads
        if (tid < TB)   sx[tid] = x[(b0 + tid) * F_SZ + f];
        if (tid < H_SZ) {
            sw1[tid]  = W1[f * H_SZ + tid];
            sb1v[tid] = b1[f * H_SZ + tid];
            sb2v[tid] = b2[f * H_SZ + tid];
            sb3v[tid] = b3[f * H_SZ + tid];
            sb4v[tid] = b4[f * H_SZ + tid];
        }
        swv[tid] = g_wv[f * T_SZ * H_SZ + tid];
        if (tid < T_SZ) sc[tid] = g_c[f * T_SZ + tid];
        __syncthreads();

        // ---- layer 1 (elementwise): sA0 = elu(x*W1 + b1) ----
#pragma unroll
        for (int idx = tid; idx < TB * H_SZ; idx += THREADS) {
            int i = idx >> 7, j = idx & 127;
            sA0[i * AP + j] = elu_f(sx[i] * sw1[j] + sb1v[j]);
        }

        unsigned long long acc[4][4];

        // ---- layer 2: sA1 = elu(sA0 @ W2 + b2) ----
        cp_wait0();              // W2 done (per-thread)
        __syncthreads();         // A0 + W2 visible to all
        issue_w(Wnxt, W3 + (long)f * H_SZ * H_SZ, tid);
        gemm_tile(sA0, Wcur, r0, c0, acc);
        epi_elu(acc, sb2v, sA1, r0, c0);
        { float* t = Wcur; Wcur = Wnxt; Wnxt = t; }

        // ---- layer 3: sA0 = elu(sA1 @ W3 + b3) ----
        cp_wait0();
        __syncthreads();         // sA1 + W3 visible; old buffer free
        issue_w(Wnxt, W4 + (long)f * H_SZ * H_SZ, tid);
        gemm_tile(sA1, Wcur, r0, c0, acc);
        epi_elu(acc, sb3v, sA0, r0, c0);
        { float* t = Wcur; Wcur = Wnxt; Wnxt = t; }

        // ---- layer 4: bb = sA0 @ W4 + b4 (no elu) ----
        cp_wait0();
        __syncthreads();
        if (ff + 1 < FG)
            issue_w(Wnxt, W2 + (long)(f + 1) * H_SZ * H_SZ, tid);
        gemm_tile(sA0, Wcur, r0, c0, acc);
        {
            float bias8[8];
            *(float4*)&bias8[0] = *(const float4*)&sb4v[c0];
            *(float4*)&bias8[4] = *(const float4*)&sb4v[c0 + 4];
#pragma unroll
            for (int r = 0; r < 4; r++) {
                float bb8[8];
#pragma unroll
                for (int c = 0; c < 4; c++) {
                    float2 v = unpack2(acc[r][c]);
                    bb8[2 * c]     = v.x + bias8[2 * c];
                    bb8[2 * c + 1] = v.y + bias8[2 * c + 1];
                }
                const int row = r0 + r;
                const int t = sa[row];
                const float* wvp = swv + t * H_SZ + c0;
                float p = 0.0f;
#pragma unroll
                for (int c = 0; c < 8; c++) {
                    bbsum[r][c] += bb8[c];
                    p += bb8[c] * wvp[c];
                }
                p += __shfl_xor_sync(0xffffffffu, p, 1, 16);
                p += __shfl_xor_sync(0xffffffffu, p, 2, 16);
                p += __shfl_xor_sync(0xffffffffu, p, 4, 16);
                p += __shfl_xor_sync(0xffffffffu, p, 8, 16);
                if (tx == 0) yacc[r] += p + sc[t];
            }
        }
        { float* t = Wcur; Wcur = Wnxt; Wnxt = t; }
    }

    // ---- final cross-feature-group reduction via fp32 atomics ----
#pragma unroll
    for (int r = 0; r < 4; r++) {
        const int row = b0 + r0 + r;
#pragma unroll
        for (int c = 0; c < 8; c++)
            atomicAdd(&out[row * H_SZ + c0 + c], bbsum[r][c]);
    }
    if (tx == 0) {
#pragma unroll
        for (int r = 0; r < 4; r++)
            atomicAdd(&out[B_SZ * H_SZ + b0 + r0 + r], yacc[r]);
    }
}

// ---------------- launch ----------------
extern "C" void kernel_launch(void* const* d_in, const int* in_sizes, int n_in,
                              void* d_out, int out_size) {
    const float* x   = (const float*)d_in[0];
    const int*   a   = (const int*)d_in[1];
    const float* W1  = (const float*)d_in[2];
    const float* b1  = (const float*)d_in[3];
    const float* W2  = (const float*)d_in[4];
    const float* b2  = (const float*)d_in[5];
    const float* W3  = (const float*)d_in[6];
    const float* b3  = (const float*)d_in[7];
    const float* W4  = (const float*)d_in[8];
    const float* b4  = (const float*)d_in[9];
    const float* Wh1 = (const float*)d_in[10];
    const float* bh1 = (const float*)d_in[11];
    const float* Wh2 = (const float*)d_in[12];
    const float* bh2 = (const float*)d_in[13];
    float* out = (float*)d_out;

    const int smem_bytes =
        (2 * TB * AP + 2 * H_SZ * H_SZ + 5 * H_SZ + T_SZ * H_SZ + T_SZ + TB) * 4
        + TB * 4;
    cudaFuncSetAttribute(nam_main, cudaFuncAttributeMaxDynamicSharedMemorySize,
                         smem_bytes);

    const int zero_blocks = (out_size + THREADS - 1) / THREADS;
    nam_setup<<<F_SZ * T_SZ + zero_blocks, THREADS>>>(out, out_size,
                                                      Wh1, bh1, Wh2, bh2);

    dim3 grid(B_SZ / TB, F_SZ / FG);
    nam_main<<<grid, THREADS, smem_bytes>>>(x, a, W1, b1, W2, b2, W3, b3, W4, b4, out);
}

// round 3
// speedup vs baseline: 1.8652x; 1.6349x over previous
#include <cuda_runtime.h>
#include <cstdint>

// Problem constants
#define B_SZ   4096
#define F_SZ   100
#define H_SZ   128
#define H2_SZ  64
#define T_SZ   2

// Tiling
#define TB      64      // batch rows per CTA tile
#define FG      5       // features per CTA
#define THREADS 256

// Precomputed collapsed head: wv[f,t,h] = sum_m Wh1[f,t,h,m]*Wh2[f,t,m]
__device__ float g_wv[F_SZ * T_SZ * H_SZ];
__device__ float g_c[F_SZ * T_SZ];

// ---------------- packed f32x2 helpers (sm_103a) ----------------
__device__ __forceinline__ unsigned long long pack_dup(float v) {
    unsigned long long r;
    asm("mov.b64 %0, {%1, %1};" : "=l"(r) : "f"(v));
    return r;
}
__device__ __forceinline__ unsigned long long fma2(unsigned long long a,
                                                   unsigned long long b,
                                                   unsigned long long c) {
    unsigned long long d;
    asm("fma.rn.f32x2 %0, %1, %2, %3;" : "=l"(d) : "l"(a), "l"(b), "l"(c));
    return d;
}
__device__ __forceinline__ float2 unpack2(unsigned long long v) {
    float2 f;
    asm("mov.b64 {%0, %1}, %2;" : "=f"(f.x), "=f"(f.y) : "l"(v));
    return f;
}
__device__ __forceinline__ float elu_f(float v) {
    return v > 0.0f ? v : (__expf(v) - 1.0f);
}

// ---------------- cp.async helpers ----------------
__device__ __forceinline__ void cp16(uint32_t saddr, const float* g) {
    asm volatile("cp.async.cg.shared.global [%0], [%1], 16;\n"
                 :: "r"(saddr), "l"(g));
}
__device__ __forceinline__ void cp_commit() {
    asm volatile("cp.async.commit_group;\n" ::: "memory");
}
__device__ __forceinline__ void cp_wait0() {
    asm volatile("cp.async.wait_group 0;\n" ::: "memory");
}
// async copy one 64KB weight matrix (H*H floats), 256 threads x 16 chunks x 16B
__device__ __forceinline__ void issue_w(float* sdst, const float* gsrc, int tid) {
    uint32_t base = (uint32_t)__cvta_generic_to_shared(sdst);
#pragma unroll
    for (int i = 0; i < 16; i++) {
        int e = (tid + i * THREADS) * 4;            // float index
        cp16(base + e * 4, gsrc + e);
    }
    cp_commit();
}

// ---------------- combined setup: zero output + head collapse ----------------
__global__ void nam_setup(float* __restrict__ out, int n_out,
                          const float* __restrict__ Wh1,
                          const float* __restrict__ bh1,
                          const float* __restrict__ Wh2,
                          const float* __restrict__ bh2) {
    const int blk = blockIdx.x;
    const int tid = threadIdx.x;
    if (blk < F_SZ * T_SZ) {
        __shared__ float s2[H2_SZ];
        if (tid < H2_SZ) s2[tid] = Wh2[blk * H2_SZ + tid];
        __syncthreads();
        if (tid < H_SZ) {
            const float* wp = Wh1 + ((long)blk * H_SZ + tid) * H2_SZ;
            float s = 0.0f;
#pragma unroll 8
            for (int m = 0; m < H2_SZ; m++) s += wp[m] * s2[m];
            g_wv[blk * H_SZ + tid] = s;
            if (tid == 0) {
                float cc = bh2[blk];
                const float* bp = bh1 + blk * H2_SZ;
                for (int m = 0; m < H2_SZ; m++) cc += bp[m] * s2[m];
                g_c[blk] = cc;
            }
        }
    } else {
        int i = (blk - F_SZ * T_SZ) * THREADS + tid;
        if (i < n_out) out[i] = 0.0f;
    }
}

// ================= GEMM tile =================
// Activation buffers are k-major (transposed): sA[c*64 + swizzled_row], where
// rows live in 16B chunks of 4; chunk index is XOR-swizzled by ((c>>2)&7) so
// both column-major epilogue stores and per-k reads are bank-conflict free.
//
// Thread tile: 8 rows (ry = tid>>5, r0 = 8*ry) x 4 cols (cx = tid&31, c0 = 4*cx).
// acc[p][j]: f32x2 holding rows (r0+2p, r0+2p+1), col c0+j.
__device__ __forceinline__ void gemm_tile(const float* __restrict__ sIn,
                                          const float* __restrict__ sW,
                                          int ry, int c0,
                                          unsigned long long acc[4][4]) {
#pragma unroll
    for (int p = 0; p < 4; p++)
#pragma unroll
        for (int j = 0; j < 4; j++) acc[p][j] = 0ull;

    const int chA = 2 * ry;        // logical chunk of rows r0..r0+3
    const int chB = 2 * ry + 1;    // logical chunk of rows r0+4..r0+7

    for (int k4 = 0; k4 < H_SZ; k4 += 4) {
        const int s = (k4 >> 2) & 7;
        const int offA = 4 * (chA ^ s);
        const int offB = 4 * (chB ^ s);
#pragma unroll
        for (int kk = 0; kk < 4; kk++) {
            const int k = k4 + kk;
            const float* ap = sIn + k * TB;
            ulonglong2 A0 = *(const ulonglong2*)(ap + offA); // rows r0..r0+3
            ulonglong2 A1 = *(const ulonglong2*)(ap + offB); // rows r0+4..r0+7
            float4 w = *(const float4*)(sW + k * H_SZ + c0);
            unsigned long long wd0 = pack_dup(w.x);
            unsigned long long wd1 = pack_dup(w.y);
            unsigned long long wd2 = pack_dup(w.z);
            unsigned long long wd3 = pack_dup(w.w);
            acc[0][0] = fma2(A0.x, wd0, acc[0][0]);
            acc[0][1] = fma2(A0.x, wd1, acc[0][1]);
            acc[0][2] = fma2(A0.x, wd2, acc[0][2]);
            acc[0][3] = fma2(A0.x, wd3, acc[0][3]);
            acc[1][0] = fma2(A0.y, wd0, acc[1][0]);
            acc[1][1] = fma2(A0.y, wd1, acc[1][1]);
            acc[1][2] = fma2(A0.y, wd2, acc[1][2]);
            acc[1][3] = fma2(A0.y, wd3, acc[1][3]);
            acc[2][0] = fma2(A1.x, wd0, acc[2][0]);
            acc[2][1] = fma2(A1.x, wd1, acc[2][1]);
            acc[2][2] = fma2(A1.x, wd2, acc[2][2]);
            acc[2][3] = fma2(A1.x, wd3, acc[2][3]);
            acc[3][0] = fma2(A1.y, wd0, acc[3][0]);
            acc[3][1] = fma2(A1.y, wd1, acc[3][1]);
            acc[3][2] = fma2(A1.y, wd2, acc[3][2]);
            acc[3][3] = fma2(A1.y, wd3, acc[3][3]);
        }
    }
}

// Epilogue with ELU, writing transposed+swizzled into sDst.
__device__ __forceinline__ void epi_elu(unsigned long long acc[4][4],
                                        const float* __restrict__ sb,
                                        float* __restrict__ sDst,
                                        int ry, int cx) {
    const int c0 = 4 * cx;
    float4 bias = *(const float4*)&sb[c0];
    const float bj[4] = {bias.x, bias.y, bias.z, bias.w};
    const int s = cx & 7;
    const int offA = 4 * ((2 * ry) ^ s);
    const int offB = 4 * ((2 * ry + 1) ^ s);
#pragma unroll
    for (int j = 0; j < 4; j++) {
        float2 v0 = unpack2(acc[0][j]);
        float2 v1 = unpack2(acc[1][j]);
        float2 v2 = unpack2(acc[2][j]);
        float2 v3 = unpack2(acc[3][j]);
        float4 lo, hi;
        lo.x = elu_f(v0.x + bj[j]);
        lo.y = elu_f(v0.y + bj[j]);
        lo.z = elu_f(v1.x + bj[j]);
        lo.w = elu_f(v1.y + bj[j]);
        hi.x = elu_f(v2.x + bj[j]);
        hi.y = elu_f(v2.y + bj[j]);
        hi.z = elu_f(v3.x + bj[j]);
        hi.w = elu_f(v3.y + bj[j]);
        float* colp = sDst + (c0 + j) * TB;
        *(float4*)(colp + offA) = lo;
        *(float4*)(colp + offB) = hi;
    }
}

// ---------------- fused main kernel ----------------
__global__ void __launch_bounds__(THREADS, 1)
nam_main(const float* __restrict__ x, const int* __restrict__ a,
         const float* __restrict__ W1, const float* __restrict__ b1,
         const float* __restrict__ W2, const float* __restrict__ b2,
         const float* __restrict__ W3, const float* __restrict__ b3,
         const float* __restrict__ W4, const float* __restrict__ b4,
         float* __restrict__ out) {
    extern __shared__ float smem[];
    float* sA0  = smem;                        // H*TB (k-major, swizzled)
    float* sA1  = sA0 + H_SZ * TB;             // H*TB
    float* sWb0 = sA1 + H_SZ * TB;             // H*H
    float* sWb1 = sWb0 + H_SZ * H_SZ;          // H*H
    float* sw1  = sWb1 + H_SZ * H_SZ;          // H
    float* sb1v = sw1 + H_SZ;                  // H
    float* sb2v = sb1v + H_SZ;                 // H
    float* sb3v = sb2v + H_SZ;                 // H
    float* sb4v = sb3v + H_SZ;                 // H
    float* swv  = sb4v + H_SZ;                 // T*H
    float* sc   = swv + T_SZ * H_SZ;           // T
    float* sx   = sc + T_SZ;                   // TB
    int*   sa   = (int*)(sx + TB);             // TB

    const int tid = threadIdx.x;
    const int cx = tid & 31;       // column group (4 cols), == lane id
    const int ry = tid >> 5;       // row group (8 rows), == warp id
    const int c0 = 4 * cx;
    const int r0 = 8 * ry;
    const int b0 = blockIdx.x * TB;
    const int fbase = blockIdx.y * FG;

    if (tid < TB) sa[tid] = a[b0 + tid];

    float bbsum[8][4];
#pragma unroll
    for (int r = 0; r < 8; r++)
#pragma unroll
        for (int j = 0; j < 4; j++) bbsum[r][j] = 0.0f;
    float yrow[8];
#pragma unroll
    for (int r = 0; r < 8; r++) yrow[r] = 0.0f;

    // prologue: async-load W2 of first feature
    float* Wcur = sWb0;
    float* Wnxt = sWb1;
    issue_w(Wcur, W2 + (long)fbase * H_SZ * H_SZ, tid);

    int ta[8];
    bool ta_loaded = false;

    for (int ff = 0; ff < FG; ff++) {
        const int f = fbase + ff;
        __syncthreads();  // protect small-load buffers + prev-feature reads

        // per-feature small loads
        if (tid < TB)   sx[tid] = x[(b0 + tid) * F_SZ + f];
        if (tid < H_SZ) {
            sw1[tid]  = W1[f * H_SZ + tid];
            sb1v[tid] = b1[f * H_SZ + tid];
            sb2v[tid] = b2[f * H_SZ + tid];
            sb3v[tid] = b3[f * H_SZ + tid];
            sb4v[tid] = b4[f * H_SZ + tid];
        }
        swv[tid] = g_wv[f * T_SZ * H_SZ + tid];
        if (tid < T_SZ) sc[tid] = g_c[f * T_SZ + tid];
        __syncthreads();

        if (!ta_loaded) {
#pragma unroll
            for (int r = 0; r < 8; r++) ta[r] = sa[r0 + r] * H_SZ;
            ta_loaded = true;
        }

        // ---- layer 1 (elementwise): sA0[j][i] = elu(x[i]*W1[j] + b1[j]) ----
#pragma unroll
        for (int t = 0; t < TB * H_SZ / THREADS; t++) {
            int idx = tid + t * THREADS;
            int j = idx >> 6;          // col 0..127
            int i = idx & 63;          // row 0..63
            float v = elu_f(sx[i] * sw1[j] + sb1v[j]);
            sA0[j * TB + 4 * ((i >> 2) ^ ((j >> 2) & 7)) + (i & 3)] = v;
        }

        unsigned long long acc[4][4];

        // ---- layer 2: sA1 = elu(sA0 @ W2 + b2) ----
        cp_wait0();              // W2 done (per-thread)
        __syncthreads();         // A0 + W2 visible to all
        issue_w(Wnxt, W3 + (long)f * H_SZ * H_SZ, tid);
        gemm_tile(sA0, Wcur, ry, c0, acc);
        epi_elu(acc, sb2v, sA1, ry, cx);
        { float* t = Wcur; Wcur = Wnxt; Wnxt = t; }

        // ---- layer 3: sA0 = elu(sA1 @ W3 + b3) ----
        cp_wait0();
        __syncthreads();
        issue_w(Wnxt, W4 + (long)f * H_SZ * H_SZ, tid);
        gemm_tile(sA1, Wcur, ry, c0, acc);
        epi_elu(acc, sb3v, sA0, ry, cx);
        { float* t = Wcur; Wcur = Wnxt; Wnxt = t; }

        // ---- layer 4: bb = sA0 @ W4 + b4 (no elu), head in registers ----
        cp_wait0();
        __syncthreads();
        if (ff + 1 < FG)
            issue_w(Wnxt, W2 + (long)(f + 1) * H_SZ * H_SZ, tid);
        gemm_tile(sA0, Wcur, ry, c0, acc);
        {
            float4 bias = *(const float4*)&sb4v[c0];
            const float bj[4] = {bias.x, bias.y, bias.z, bias.w};
            float bb[8][4];
#pragma unroll
            for (int p = 0; p < 4; p++)
#pragma unroll
                for (int j = 0; j < 4; j++) {
                    float2 v = unpack2(acc[p][j]);
                    bb[2 * p][j]     = v.x + bj[j];
                    bb[2 * p + 1][j] = v.y + bj[j];
                }
#pragma unroll
            for (int r = 0; r < 8; r++) {
                const float* wp = swv + ta[r] + c0;
                float pr = 0.0f;
#pragma unroll
                for (int j = 0; j < 4; j++) {
                    bbsum[r][j] += bb[r][j];
                    pr += bb[r][j] * wp[j];
                }
                yrow[r] += pr;
            }
            if (cx == 0) {
#pragma unroll
                for (int r = 0; r < 8; r++) yrow[r] += sc[ta[r] >> 7];
            }
        }
        { float* t = Wcur; Wcur = Wnxt; Wnxt = t; }
    }

    // ---- final cross-feature-group reduction via fp32 atomics ----
#pragma unroll
    for (int r = 0; r < 8; r++) {
        const int row = b0 + r0 + r;
#pragma unroll
        for (int j = 0; j < 4; j++)
            atomicAdd(&out[row * H_SZ + c0 + j], bbsum[r][j]);
    }
#pragma unroll
    for (int r = 0; r < 8; r++) {
        float v = yrow[r];
        v += __shfl_xor_sync(0xffffffffu, v, 16);
        v += __shfl_xor_sync(0xffffffffu, v, 8);
        v += __shfl_xor_sync(0xffffffffu, v, 4);
        v += __shfl_xor_sync(0xffffffffu, v, 2);
        v += __shfl_xor_sync(0xffffffffu, v, 1);
        if (cx == 0) atomicAdd(&out[B_SZ * H_SZ + b0 + r0 + r], v);
    }
}

// ---------------- launch ----------------
extern "C" void kernel_launch(void* const* d_in, const int* in_sizes, int n_in,
                              void* d_out, int out_size) {
    const float* x   = (const float*)d_in[0];
    const int*   a   = (const int*)d_in[1];
    const float* W1  = (const float*)d_in[2];
    const float* b1  = (const float*)d_in[3];
    const float* W2  = (const float*)d_in[4];
    const float* b2  = (const float*)d_in[5];
    const float* W3  = (const float*)d_in[6];
    const float* b3  = (const float*)d_in[7];
    const float* W4  = (const float*)d_in[8];
    const float* b4  = (const float*)d_in[9];
    const float* Wh1 = (const float*)d_in[10];
    const float* bh1 = (const float*)d_in[11];
    const float* Wh2 = (const float*)d_in[12];
    const float* bh2 = (const float*)d_in[13];
    float* out = (float*)d_out;

    const int smem_bytes =
        (2 * H_SZ * TB + 2 * H_SZ * H_SZ + 5 * H_SZ + T_SZ * H_SZ + T_SZ + TB) * 4
        + TB * 4;
    cudaFuncSetAttribute(nam_main, cudaFuncAttributeMaxDynamicSharedMemorySize,
                         smem_bytes);

    const int zero_blocks = (out_size + THREADS - 1) / THREADS;
    nam_setup<<<F_SZ * T_SZ + zero_blocks, THREADS>>>(out, out_size,
                                                      Wh1, bh1, Wh2, bh2);

    dim3 grid(B_SZ / TB, F_SZ / FG);
    nam_main<<<grid, THREADS, smem_bytes>>>(x, a, W1, b1, W2, b2, W3, b3, W4, b4, out);
}

// round 4
// speedup vs baseline: 2.0625x; 1.1057x over previous
#include <cuda_runtime.h>
#include <cstdint>

// Problem constants
#define B_SZ   4096
#define F_SZ   100
#define H_SZ   128
#define H2_SZ  64
#define T_SZ   2
#define HH     (H_SZ * H_SZ)
#define HALF   (64 * H_SZ)      // floats per half weight matrix (32KB)

// Tiling
#define TB      64      // batch rows per CTA tile
#define FG      5       // features per CTA
#define THREADS 256

// Precomputed collapsed head: wv[f,t,h] = sum_m Wh1[f,t,h,m]*Wh2[f,t,m]
__device__ float g_wv[F_SZ * T_SZ * H_SZ];
__device__ float g_c[F_SZ * T_SZ];

// ---------------- packed f32x2 helpers (sm_103a) ----------------
__device__ __forceinline__ unsigned long long pack_dup(float v) {
    unsigned long long r;
    asm("mov.b64 %0, {%1, %1};" : "=l"(r) : "f"(v));
    return r;
}
__device__ __forceinline__ unsigned long long fma2(unsigned long long a,
                                                   unsigned long long b,
                                                   unsigned long long c) {
    unsigned long long d;
    asm("fma.rn.f32x2 %0, %1, %2, %3;" : "=l"(d) : "l"(a), "l"(b), "l"(c));
    return d;
}
__device__ __forceinline__ float2 unpack2(unsigned long long v) {
    float2 f;
    asm("mov.b64 {%0, %1}, %2;" : "=f"(f.x), "=f"(f.y) : "l"(v));
    return f;
}
__device__ __forceinline__ float elu_f(float v) {
    return v > 0.0f ? v : (__expf(v) - 1.0f);
}

// ---------------- cp.async helpers ----------------
__device__ __forceinline__ void cp16(uint32_t saddr, const float* g) {
    asm volatile("cp.async.cg.shared.global [%0], [%1], 16;\n"
                 :: "r"(saddr), "l"(g));
}
__device__ __forceinline__ void cp_commit() {
    asm volatile("cp.async.commit_group;\n" ::: "memory");
}
__device__ __forceinline__ void cp_wait0() {
    asm volatile("cp.async.wait_group 0;\n" ::: "memory");
}
__device__ __forceinline__ void cp_wait1() {
    asm volatile("cp.async.wait_group 1;\n" ::: "memory");
}
// async copy one 32KB half weight matrix (64*H floats)
__device__ __forceinline__ void issue_half(float* sdst, const float* gsrc, int tid) {
    uint32_t base = (uint32_t)__cvta_generic_to_shared(sdst);
#pragma unroll
    for (int i = 0; i < 8; i++) {
        int e = (tid + i * THREADS) * 4;            // float index
        cp16(base + e * 4, gsrc + e);
    }
    cp_commit();
}

// ---------------- combined setup: zero output + head collapse ----------------
__global__ void nam_setup(float* __restrict__ out, int n_out,
                          const float* __restrict__ Wh1,
                          const float* __restrict__ bh1,
                          const float* __restrict__ Wh2,
                          const float* __restrict__ bh2) {
    const int blk = blockIdx.x;
    const int tid = threadIdx.x;
    if (blk < F_SZ * T_SZ) {
        __shared__ float s2[H2_SZ];
        if (tid < H2_SZ) s2[tid] = Wh2[blk * H2_SZ + tid];
        __syncthreads();
        if (tid < H_SZ) {
            const float* wp = Wh1 + ((long)blk * H_SZ + tid) * H2_SZ;
            float s = 0.0f;
#pragma unroll 8
            for (int m = 0; m < H2_SZ; m++) s += wp[m] * s2[m];
            g_wv[blk * H_SZ + tid] = s;
            if (tid == 0) {
                float cc = bh2[blk];
                const float* bp = bh1 + blk * H2_SZ;
                for (int m = 0; m < H2_SZ; m++) cc += bp[m] * s2[m];
                g_c[blk] = cc;
            }
        }
    } else {
        int i = (blk - F_SZ * T_SZ) * THREADS + tid;
        if (i < n_out) out[i] = 0.0f;
    }
}

// ================= half GEMM =================
// Activations: k-major transposed, rows in 16B chunks of 4, chunk XOR-swizzled
// by ((k>>2)&7). Thread tile: 8 rows (ry=tid>>5) x 4 cols (cx=tid&31).
// acc[p][j]: f32x2 of rows (8ry+2p, 8ry+2p+1), col 4cx+j.
// Processes k in [kbase, kbase+64) with weights in sWh (local k index).
__device__ __forceinline__ void gemm_half(const float* __restrict__ sIn,
                                          const float* __restrict__ sWh,
                                          int ry, int c0, int kbase,
                                          unsigned long long acc[4][4]) {
    const int chA = 2 * ry;
    const int chB = 2 * ry + 1;
    const float* wp = sWh + c0;
    const float* ain = sIn + kbase * TB;

    for (int kl4 = 0; kl4 < 64; kl4 += 4) {
        const int s = (kl4 >> 2) & 7;          // (64+kl4)>>2 is congruent mod 8
        const int offA = 4 * (chA ^ s);
        const int offB = 4 * (chB ^ s);
#pragma unroll
        for (int kk = 0; kk < 4; kk++) {
            ulonglong2 A0 = *(const ulonglong2*)(ain + offA);
            ulonglong2 A1 = *(const ulonglong2*)(ain + offB);
            float4 w = *(const float4*)wp;
            wp += H_SZ;
            ain += TB;
            unsigned long long wd0 = pack_dup(w.x);
            unsigned long long wd1 = pack_dup(w.y);
            unsigned long long wd2 = pack_dup(w.z);
            unsigned long long wd3 = pack_dup(w.w);
            acc[0][0] = fma2(A0.x, wd0, acc[0][0]);
            acc[0][1] = fma2(A0.x, wd1, acc[0][1]);
            acc[0][2] = fma2(A0.x, wd2, acc[0][2]);
            acc[0][3] = fma2(A0.x, wd3, acc[0][3]);
            acc[1][0] = fma2(A0.y, wd0, acc[1][0]);
            acc[1][1] = fma2(A0.y, wd1, acc[1][1]);
            acc[1][2] = fma2(A0.y, wd2, acc[1][2]);
            acc[1][3] = fma2(A0.y, wd3, acc[1][3]);
            acc[2][0] = fma2(A1.x, wd0, acc[2][0]);
            acc[2][1] = fma2(A1.x, wd1, acc[2][1]);
            acc[2][2] = fma2(A1.x, wd2, acc[2][2]);
            acc[2][3] = fma2(A1.x, wd3, acc[2][3]);
            acc[3][0] = fma2(A1.y, wd0, acc[3][0]);
            acc[3][1] = fma2(A1.y, wd1, acc[3][1]);
            acc[3][2] = fma2(A1.y, wd2, acc[3][2]);
            acc[3][3] = fma2(A1.y, wd3, acc[3][3]);
        }
    }
}

// Epilogue with ELU, writing transposed+swizzled (in-place safe after barrier).
__device__ __forceinline__ void epi_elu(unsigned long long acc[4][4],
                                        const float* __restrict__ sb,
                                        float* __restrict__ sDst,
                                        int ry, int cx) {
    const int c0 = 4 * cx;
    float4 bias = *(const float4*)&sb[c0];
    const float bj[4] = {bias.x, bias.y, bias.z, bias.w};
    const int s = cx & 7;
    const int offA = 4 * ((2 * ry) ^ s);
    const int offB = 4 * ((2 * ry + 1) ^ s);
#pragma unroll
    for (int j = 0; j < 4; j++) {
        float2 v0 = unpack2(acc[0][j]);
        float2 v1 = unpack2(acc[1][j]);
        float2 v2 = unpack2(acc[2][j]);
        float2 v3 = unpack2(acc[3][j]);
        float4 lo, hi;
        lo.x = elu_f(v0.x + bj[j]);
        lo.y = elu_f(v0.y + bj[j]);
        lo.z = elu_f(v1.x + bj[j]);
        lo.w = elu_f(v1.y + bj[j]);
        hi.x = elu_f(v2.x + bj[j]);
        hi.y = elu_f(v2.y + bj[j]);
        hi.z = elu_f(v3.x + bj[j]);
        hi.w = elu_f(v3.y + bj[j]);
        float* colp = sDst + (c0 + j) * TB;
        *(float4*)(colp + offA) = lo;
        *(float4*)(colp + offB) = hi;
    }
}

// ---------------- fused main kernel ----------------
__global__ void __launch_bounds__(THREADS, 2)
nam_main(const float* __restrict__ x, const int* __restrict__ a,
         const float* __restrict__ W1, const float* __restrict__ b1,
         const float* __restrict__ W2, const float* __restrict__ b2,
         const float* __restrict__ W3, const float* __restrict__ b3,
         const float* __restrict__ W4, const float* __restrict__ b4,
         float* __restrict__ out) {
    extern __shared__ float smem[];
    float* sA    = smem;                       // H*TB (k-major, swizzled) 8192
    float* sWA   = sA + H_SZ * TB;             // 8192 (half0: k 0..63)
    float* sWB   = sWA + HALF;                 // 8192 (half1: k 64..127)
    float* sw1   = sWB + HALF;                 // 128
    float* sb1v  = sw1 + H_SZ;                 // 128
    float* sb234 = sb1v + H_SZ;                // 3*128
    float* swv   = sb234 + 3 * H_SZ;           // T*H = 256
    float* sc    = swv + T_SZ * H_SZ;          // 2
    float* sx    = sc + T_SZ;                  // 64
    int*   sa    = (int*)(sx + TB);            // 64

    const int tid = threadIdx.x;
    const int cx = tid & 31;       // lane: 4 cols
    const int ry = tid >> 5;       // warp: 8 rows
    const int c0 = 4 * cx;
    const int r0 = 8 * ry;
    const int b0 = blockIdx.x * TB;
    const int fbase = blockIdx.y * FG;

    if (tid < TB) sa[tid] = a[b0 + tid];

    float bbsum[8][4];
#pragma unroll
    for (int r = 0; r < 8; r++)
#pragma unroll
        for (int j = 0; j < 4; j++) bbsum[r][j] = 0.0f;
    float yrow[8];
#pragma unroll
    for (int r = 0; r < 8; r++) yrow[r] = 0.0f;

    // prologue: stream both halves of first feature's W2
    issue_half(sWA, W2 + (long)fbase * HH, tid);
    issue_half(sWB, W2 + (long)fbase * HH + HALF, tid);

    for (int ff = 0; ff < FG; ff++) {
        const int f = fbase + ff;
        __syncthreads();  // guard small buffers & prev-feature epilogue reads

        // per-feature small loads
        if (tid < TB)   sx[tid] = x[(b0 + tid) * F_SZ + f];
        if (tid < H_SZ) {
            sw1[tid]   = W1[f * H_SZ + tid];
            sb1v[tid]  = b1[f * H_SZ + tid];
            sb234[tid]            = b2[f * H_SZ + tid];
            sb234[H_SZ + tid]     = b3[f * H_SZ + tid];
            sb234[2 * H_SZ + tid] = b4[f * H_SZ + tid];
        }
        swv[tid] = g_wv[f * T_SZ * H_SZ + tid];
        if (tid < T_SZ) sc[tid] = g_c[f * T_SZ + tid];
        __syncthreads();

        // ---- layer 1 (elementwise): sA[j][i] = elu(x[i]*W1[j] + b1[j]) ----
#pragma unroll
        for (int t = 0; t < TB * H_SZ / THREADS; t++) {
            int idx = tid + t * THREADS;
            int j = idx >> 6;          // col 0..127
            int i = idx & 63;          // row 0..63
            float v = elu_f(sx[i] * sw1[j] + sb1v[j]);
            sA[j * TB + 4 * ((i >> 2) ^ ((j >> 2) & 7)) + (i & 3)] = v;
        }

        const float* nexts[3];
        nexts[0] = W3 + (long)f * HH;
        nexts[1] = W4 + (long)f * HH;
        nexts[2] = (ff + 1 < FG) ? (W2 + (long)(f + 1) * HH) : nullptr;

#pragma unroll
        for (int l = 0; l < 3; l++) {
            unsigned long long acc[4][4];
#pragma unroll
            for (int p = 0; p < 4; p++)
#pragma unroll
                for (int j = 0; j < 4; j++) acc[p][j] = 0ull;

            const float* nx = nexts[l];

            cp_wait1();               // half0 of current layer ready
            __syncthreads();          // + layer1/epilogue stores visible
            gemm_half(sA, sWA, ry, c0, 0, acc);
            __syncthreads();          // all reads of sWA done
            if (nx) issue_half(sWA, nx, tid);
            if (nx) cp_wait1(); else cp_wait0();   // half1 ready
            __syncthreads();
            gemm_half(sA, sWB, ry, c0, 64, acc);
            __syncthreads();          // all reads of sWB + sA done
            if (nx) issue_half(sWB, nx + HALF, tid);

            if (l < 2) {
                epi_elu(acc, sb234 + l * H_SZ, sA, ry, cx);
            } else {
                // ---- layer 4 epilogue: bb + head, no ELU ----
                float4 bias = *(const float4*)&sb234[2 * H_SZ + c0];
                const float bj[4] = {bias.x, bias.y, bias.z, bias.w};
                float bb[8][4];
#pragma unroll
                for (int p = 0; p < 4; p++)
#pragma unroll
                    for (int j = 0; j < 4; j++) {
                        float2 v = unpack2(acc[p][j]);
                        bb[2 * p][j]     = v.x + bj[j];
                        bb[2 * p + 1][j] = v.y + bj[j];
                    }
#pragma unroll
                for (int r = 0; r < 8; r++) {
                    const int t = sa[r0 + r];
                    float4 wv4 = *(const float4*)(swv + t * H_SZ + c0);
                    float pr = bb[r][0] * wv4.x + bb[r][1] * wv4.y +
                               bb[r][2] * wv4.z + bb[r][3] * wv4.w;
#pragma unroll
                    for (int j = 0; j < 4; j++) bbsum[r][j] += bb[r][j];
                    if (cx == 0) pr += sc[t];
                    yrow[r] += pr;
                }
            }
        }
    }

    // ---- final cross-feature-group reduction via fp32 atomics ----
#pragma unroll
    for (int r = 0; r < 8; r++) {
        const int row = b0 + r0 + r;
#pragma unroll
        for (int j = 0; j < 4; j++)
            atomicAdd(&out[row * H_SZ + c0 + j], bbsum[r][j]);
    }
#pragma unroll
    for (int r = 0; r < 8; r++) {
        float v = yrow[r];
        v += __shfl_xor_sync(0xffffffffu, v, 16);
        v += __shfl_xor_sync(0xffffffffu, v, 8);
        v += __shfl_xor_sync(0xffffffffu, v, 4);
        v += __shfl_xor_sync(0xffffffffu, v, 2);
        v += __shfl_xor_sync(0xffffffffu, v, 1);
        if (cx == 0) atomicAdd(&out[B_SZ * H_SZ + b0 + r0 + r], v);
    }
}

// ---------------- launch ----------------
extern "C" void kernel_launch(void* const* d_in, const int* in_sizes, int n_in,
                              void* d_out, int out_size) {
    const float* x   = (const float*)d_in[0];
    const int*   a   = (const int*)d_in[1];
    const float* W1  = (const float*)d_in[2];
    const float* b1  = (const float*)d_in[3];
    const float* W2  = (const float*)d_in[4];
    const float* b2  = (const float*)d_in[5];
    const float* W3  = (const float*)d_in[6];
    const float* b3  = (const float*)d_in[7];
    const float* W4  = (const float*)d_in[8];
    const float* b4  = (const float*)d_in[9];
    const float* Wh1 = (const float*)d_in[10];
    const float* bh1 = (const float*)d_in[11];
    const float* Wh2 = (const float*)d_in[12];
    const float* bh2 = (const float*)d_in[13];
    float* out = (float*)d_out;

    const int smem_floats = H_SZ * TB + 2 * HALF + 2 * H_SZ + 3 * H_SZ +
                            T_SZ * H_SZ + T_SZ + TB;
    const int smem_bytes = smem_floats * 4 + TB * 4;
    cudaFuncSetAttribute(nam_main, cudaFuncAttributeMaxDynamicSharedMemorySize,
                         smem_bytes);

    const int zero_blocks = (out_size + THREADS - 1) / THREADS;
    nam_setup<<<F_SZ * T_SZ + zero_blocks, THREADS>>>(out, out_size,
                                                      Wh1, bh1, Wh2, bh2);

    dim3 grid(B_SZ / TB, F_SZ / FG);
    nam_main<<<grid, THREADS, smem_bytes>>>(x, a, W1, b1, W2, b2, W3, b3, W4, b4, out);
}

// round 6
// speedup vs baseline: 3.8340x; 1.8589x over previous
#include <cuda_runtime.h>
#include <cuda_bf16.h>
#include <cstdint>

// Problem constants
#define B_SZ   4096
#define F_SZ   100
#define H_SZ   128
#define H2_SZ  64
#define T_SZ   2

// Tiling
#define TB      128     // batch rows per CTA (8 warps x 16-row M-stripes)
#define FG      5       // features per CTA
#define THREADS 256
#define WB32    8192    // uint32 entries per packed weight matrix (32KB)

// Fragment-packed bf16 split weights: [layer][f][hi/lo][8192] uint32 (bf16x2)
// entry e = ((ks*16 + nt)*32 + lane); regs at 2e, 2e+1
__device__ uint32_t g_wp[3][F_SZ][2][2 * WB32 / 2];   // [3][F][2][8192]
// Collapsed head
__device__ float g_wv[F_SZ * T_SZ * H_SZ];
__device__ float g_c[F_SZ * T_SZ];

// ---------------- scalar helpers ----------------
__device__ __forceinline__ float elu_f(float v) {
    return v > 0.0f ? v : (__expf(v) - 1.0f);
}
// pack two fp32 to bf16x2 (low half = v0), return residuals
__device__ __forceinline__ uint32_t pack_split(float v0, float v1, float& r0, float& r1) {
    uint32_t p;
    asm("cvt.rn.bf16x2.f32 %0, %1, %2;" : "=r"(p) : "f"(v1), "f"(v0));
    float f0, f1;
    asm("{.reg .b16 l,h; mov.b32 {l,h}, %2; cvt.f32.bf16 %0, l; cvt.f32.bf16 %1, h;}"
        : "=f"(f0), "=f"(f1) : "r"(p));
    r0 = v0 - f0; r1 = v1 - f1;
    return p;
}
__device__ __forceinline__ uint32_t pack2bf(float v0, float v1) {
    uint32_t p;
    asm("cvt.rn.bf16x2.f32 %0, %1, %2;" : "=r"(p) : "f"(v1), "f"(v0));
    return p;
}

// mma.sync m16n8k16 bf16 (baseline PTX, no 'a' feature needed)
__device__ __forceinline__ void mma16816(float d[4], const uint32_t a[4],
                                         uint32_t b0, uint32_t b1) {
    asm("mma.sync.aligned.m16n8k16.row.col.f32.bf16.bf16.f32 "
        "{%0,%1,%2,%3}, {%4,%5,%6,%7}, {%8,%9}, {%0,%1,%2,%3};"
        : "+f"(d[0]), "+f"(d[1]), "+f"(d[2]), "+f"(d[3])
        : "r"(a[0]), "r"(a[1]), "r"(a[2]), "r"(a[3]), "r"(b0), "r"(b1));
}

// ---------------- cp.async ----------------
__device__ __forceinline__ void cp16(uint32_t saddr, const void* g) {
    asm volatile("cp.async.cg.shared.global [%0], [%1], 16;\n" :: "r"(saddr), "l"(g));
}
__device__ __forceinline__ void cp_commit() {
    asm volatile("cp.async.commit_group;\n" ::: "memory");
}
__device__ __forceinline__ void cp_wait0() {
    asm volatile("cp.async.wait_group 0;\n" ::: "memory");
}
// copy one 64KB packed weight block (hi 32KB + lo 32KB contiguous)
__device__ __forceinline__ void issue_w(uint32_t sdst, const char* gsrc, int tid) {
#pragma unroll
    for (int i = 0; i < 16; i++) {
        int b = (tid + i * THREADS) * 16;
        cp16(sdst + b, gsrc + b);
    }
    cp_commit();
}

// ---------------- setup: pack weights, head collapse, zero out ----------------
__global__ void nam_setup(float* __restrict__ out, int n_out,
                          const float* __restrict__ W2, const float* __restrict__ W3,
                          const float* __restrict__ W4,
                          const float* __restrict__ Wh1, const float* __restrict__ bh1,
                          const float* __restrict__ Wh2, const float* __restrict__ bh2) {
    const int blk = blockIdx.x;
    const int tid = threadIdx.x;
    if (blk < 3 * F_SZ) {
        const int l = blk / F_SZ, f = blk % F_SZ;
        const float* W = (l == 0 ? W2 : (l == 1 ? W3 : W4)) + (long)f * H_SZ * H_SZ;
        uint32_t* hi = &g_wp[l][f][0][0];
        uint32_t* lo = &g_wp[l][f][1][0];
        for (int e = tid; e < 4096; e += THREADS) {
            // e = (ks*16 + nt)*32 + lane
            const int lane = e & 31;
            const int t = lane & 3, g = lane >> 2;
            const int nt = (e >> 5) & 15, ks = e >> 9;
            const int n = nt * 8 + g;
            const int k0 = ks * 16 + t * 2;
            float w00 = W[(k0)     * H_SZ + n];
            float w01 = W[(k0 + 1) * H_SZ + n];
            float w10 = W[(k0 + 8) * H_SZ + n];
            float w11 = W[(k0 + 9) * H_SZ + n];
            float r00, r01, r10, r11;
            uint32_t h0 = pack_split(w00, w01, r00, r01);
            uint32_t h1 = pack_split(w10, w11, r10, r11);
            hi[2 * e]     = h0;
            hi[2 * e + 1] = h1;
            lo[2 * e]     = pack2bf(r00, r01);
            lo[2 * e + 1] = pack2bf(r10, r11);
        }
    } else if (blk < 3 * F_SZ + F_SZ * T_SZ) {
        const int ft = blk - 3 * F_SZ;
        __shared__ float s2[H2_SZ];
        if (tid < H2_SZ) s2[tid] = Wh2[ft * H2_SZ + tid];
        __syncthreads();
        if (tid < H_SZ) {
            const float* wp = Wh1 + ((long)ft * H_SZ + tid) * H2_SZ;
            float s = 0.0f;
#pragma unroll 8
            for (int m = 0; m < H2_SZ; m++) s += wp[m] * s2[m];
            g_wv[ft * H_SZ + tid] = s;
            if (tid == 0) {
                float cc = bh2[ft];
                const float* bp = bh1 + ft * H2_SZ;
                for (int m = 0; m < H2_SZ; m++) cc += bp[m] * s2[m];
                g_c[ft] = cc;
            }
        }
    } else {
        int i = (blk - (3 * F_SZ + F_SZ * T_SZ)) * THREADS + tid;
        if (i < n_out) out[i] = 0.0f;
    }
}

// ---------------- fused main kernel ----------------
// smem: [0,64K) Wbuf0, [64K,128K) Wbuf1, then float area
#define FS_OFF  131072
#define SX_I    0        // 128
#define SW1_I   128      // 128
#define SB1_I   256      // 128
#define SB2_I   384      // 3*128 (b2,b3,b4)
#define SWV_I   768      // 256
#define SC_I    1024     // 2
#define SMEM_BYTES (FS_OFF + (SC_I + 2) * 4)

__global__ void __launch_bounds__(THREADS, 1)
nam_main(const float* __restrict__ x, const int* __restrict__ a,
         const float* __restrict__ W1, const float* __restrict__ b1,
         const float* __restrict__ b2, const float* __restrict__ b3,
         const float* __restrict__ b4, float* __restrict__ out) {
    extern __shared__ char smem[];
    float* fs  = (float*)(smem + FS_OFF);
    float* sx  = fs + SX_I;
    float* sw1 = fs + SW1_I;
    float* sb1 = fs + SB1_I;
    float* sbias = fs + SB2_I;      // b2 | b3 | b4
    float* swv = fs + SWV_I;
    float* sc  = fs + SC_I;

    const int tid = threadIdx.x;
    const int w = tid >> 5, lane = tid & 31;
    const int t = lane & 3, g = lane >> 2;
    const int t2 = t * 2;
    const int lr0 = 16 * w + g;     // local row (acc c0/c1)
    const int lr1 = lr0 + 8;        // local row (acc c2/c3)
    const int b0 = blockIdx.x * TB;
    const int fbase = blockIdx.y * FG;
    const int grow0 = b0 + lr0, grow1 = b0 + lr1;

    const uint32_t smem_u32 = (uint32_t)__cvta_generic_to_shared(smem);

    const int t0 = a[grow0], t1 = a[grow1];
    const int t0w = t0 * H_SZ, t1w = t1 * H_SZ;

    float acc[16][4];
    uint32_t Ah[8][4], Al[8][4];
    float bbs[16][4];
#pragma unroll
    for (int nt = 0; nt < 16; nt++)
#pragma unroll
        for (int j = 0; j < 4; j++) bbs[nt][j] = 0.0f;
    float yacc0 = 0.0f, yacc1 = 0.0f;

    // prologue: first feature's layer-2 weights -> buf0
    issue_w(smem_u32, (const char*)&g_wp[0][fbase][0][0], tid);
    int buf = 0;

    for (int ff = 0; ff < FG; ff++) {
        const int f = fbase + ff;
        __syncthreads();   // prev feature done reading small buffers
        if (tid < 128) {
            sx[tid]          = x[(long)(b0 + tid) * F_SZ + f];
            sw1[tid]         = W1[f * H_SZ + tid];
            sb1[tid]         = b1[f * H_SZ + tid];
            sbias[tid]       = b2[f * H_SZ + tid];
            sbias[128 + tid] = b3[f * H_SZ + tid];
            sbias[256 + tid] = b4[f * H_SZ + tid];
        }
        swv[tid] = g_wv[f * 256 + tid];
        if (tid < 2) sc[tid] = g_c[f * 2 + tid];
        __syncthreads();

        // ---- layer 1: build A-fragments directly (hi/lo bf16 split) ----
        {
            const float xv0 = sx[lr0], xv1 = sx[lr1];
#pragma unroll
            for (int kk = 0; kk < 8; kk++) {
                const int cA = 16 * kk + t2, cB = cA + 8;
                float2 wA = *(const float2*)&sw1[cA];
                float2 bA = *(const float2*)&sb1[cA];
                float2 wB = *(const float2*)&sw1[cB];
                float2 bB = *(const float2*)&sb1[cB];
                float r0, r1;
                float v0 = elu_f(xv0 * wA.x + bA.x);
                float v1 = elu_f(xv0 * wA.y + bA.y);
                Ah[kk][0] = pack_split(v0, v1, r0, r1); Al[kk][0] = pack2bf(r0, r1);
                v0 = elu_f(xv1 * wA.x + bA.x);
                v1 = elu_f(xv1 * wA.y + bA.y);
                Ah[kk][1] = pack_split(v0, v1, r0, r1); Al[kk][1] = pack2bf(r0, r1);
                v0 = elu_f(xv0 * wB.x + bB.x);
                v1 = elu_f(xv0 * wB.y + bB.y);
                Ah[kk][2] = pack_split(v0, v1, r0, r1); Al[kk][2] = pack2bf(r0, r1);
                v0 = elu_f(xv1 * wB.x + bB.x);
                v1 = elu_f(xv1 * wB.y + bB.y);
                Ah[kk][3] = pack_split(v0, v1, r0, r1); Al[kk][3] = pack2bf(r0, r1);
            }
        }

#pragma unroll 1
        for (int l = 0; l < 3; l++) {
            cp_wait0();
            __syncthreads();   // current buf ready; other buf fully consumed

            const char* nxt = (l < 2) ? (const char*)&g_wp[l + 1][f][0][0]
                              : ((ff + 1 < FG) ? (const char*)&g_wp[0][f + 1][0][0]
                                               : nullptr);
            if (nxt) issue_w(smem_u32 + (buf ? 0u : 65536u), nxt, tid);

            // ---- 3-pass split GEMM on current buffer ----
            {
                const uint32_t* Wh = (const uint32_t*)(smem + (buf ? 65536 : 0));
                const uint32_t* Wl = Wh + WB32;
#pragma unroll
                for (int nt = 0; nt < 16; nt++) {
                    acc[nt][0] = 0.f; acc[nt][1] = 0.f;
                    acc[nt][2] = 0.f; acc[nt][3] = 0.f;
                }
#pragma unroll
                for (int ks = 0; ks < 8; ks++) {
                    const uint32_t* bh = Wh + ks * 1024 + lane * 2;
                    const uint32_t* bl = Wl + ks * 1024 + lane * 2;
#pragma unroll
                    for (int nt = 0; nt < 16; nt++) {
                        uint2 wh = *(const uint2*)(bh + nt * 64);
                        uint2 wl = *(const uint2*)(bl + nt * 64);
                        mma16816(acc[nt], Ah[ks], wh.x, wh.y);
                        mma16816(acc[nt], Al[ks], wh.x, wh.y);
                        mma16816(acc[nt], Ah[ks], wl.x, wl.y);
                    }
                }
            }

            if (l < 2) {
                // ---- epilogue: bias + ELU + split -> next layer's A frags ----
                const float* sb = sbias + l * 128;
#pragma unroll
                for (int kk = 0; kk < 8; kk++) {
                    const int nt0 = 2 * kk, nt1 = 2 * kk + 1;
                    float2 bA = *(const float2*)&sb[8 * nt0 + t2];
                    float2 bB = *(const float2*)&sb[8 * nt1 + t2];
                    float r0, r1;
                    float v0 = elu_f(acc[nt0][0] + bA.x);
                    float v1 = elu_f(acc[nt0][1] + bA.y);
                    Ah[kk][0] = pack_split(v0, v1, r0, r1); Al[kk][0] = pack2bf(r0, r1);
                    v0 = elu_f(acc[nt0][2] + bA.x);
                    v1 = elu_f(acc[nt0][3] + bA.y);
                    Ah[kk][1] = pack_split(v0, v1, r0, r1); Al[kk][1] = pack2bf(r0, r1);
                    v0 = elu_f(acc[nt1][0] + bB.x);
                    v1 = elu_f(acc[nt1][1] + bB.y);
                    Ah[kk][2] = pack_split(v0, v1, r0, r1); Al[kk][2] = pack2bf(r0, r1);
                    v0 = elu_f(acc[nt1][2] + bB.x);
                    v1 = elu_f(acc[nt1][3] + bB.y);
                    Ah[kk][3] = pack_split(v0, v1, r0, r1); Al[kk][3] = pack2bf(r0, r1);
                }
            } else {
                // ---- layer-4 epilogue: bb accumulate + collapsed head ----
                const float* sb4 = sbias + 256;
                float y0 = 0.0f, y1 = 0.0f;
#pragma unroll
                for (int nt = 0; nt < 16; nt++) {
                    float2 b4v = *(const float2*)&sb4[8 * nt + t2];
                    float bb0 = acc[nt][0] + b4v.x;
                    float bb1 = acc[nt][1] + b4v.y;
                    float bb2 = acc[nt][2] + b4v.x;
                    float bb3 = acc[nt][3] + b4v.y;
                    bbs[nt][0] += bb0; bbs[nt][1] += bb1;
                    bbs[nt][2] += bb2; bbs[nt][3] += bb3;
                    float2 wv0 = *(const float2*)&swv[t0w + 8 * nt + t2];
                    float2 wv1 = *(const float2*)&swv[t1w + 8 * nt + t2];
                    y0 += bb0 * wv0.x + bb1 * wv0.y;
                    y1 += bb2 * wv1.x + bb3 * wv1.y;
                }
                if (t == 0) { y0 += sc[t0]; y1 += sc[t1]; }
                yacc0 += y0; yacc1 += y1;
            }
            buf ^= 1;
        }
    }

    // ---- finale: atomics into output ----
#pragma unroll
    for (int nt = 0; nt < 16; nt++) {
        const int col = 8 * nt + t2;
        atomicAdd(&out[(long)grow0 * H_SZ + col],     bbs[nt][0]);
        atomicAdd(&out[(long)grow0 * H_SZ + col + 1], bbs[nt][1]);
        atomicAdd(&out[(long)grow1 * H_SZ + col],     bbs[nt][2]);
        atomicAdd(&out[(long)grow1 * H_SZ + col + 1], bbs[nt][3]);
    }
    yacc0 += __shfl_xor_sync(0xffffffffu, yacc0, 1);
    yacc0 += __shfl_xor_sync(0xffffffffu, yacc0, 2);
    yacc1 += __shfl_xor_sync(0xffffffffu, yacc1, 1);
    yacc1 += __shfl_xor_sync(0xffffffffu, yacc1, 2);
    if (t == 0) {
        atomicAdd(&out[B_SZ * H_SZ + grow0], yacc0);
        atomicAdd(&out[B_SZ * H_SZ + grow1], yacc1);
    }
}

// ---------------- launch ----------------
extern "C" void kernel_launch(void* const* d_in, const int* in_sizes, int n_in,
                              void* d_out, int out_size) {
    const float* x   = (const float*)d_in[0];
    const int*   a   = (const int*)d_in[1];
    const float* W1  = (const float*)d_in[2];
    const float* b1  = (const float*)d_in[3];
    const float* W2  = (const float*)d_in[4];
    const float* b2  = (const float*)d_in[5];
    const float* W3  = (const float*)d_in[6];
    const float* b3  = (const float*)d_in[7];
    const float* W4  = (const float*)d_in[8];
    const float* b4  = (const float*)d_in[9];
    const float* Wh1 = (const float*)d_in[10];
    const float* bh1 = (const float*)d_in[11];
    const float* Wh2 = (const float*)d_in[12];
    const float* bh2 = (const float*)d_in[13];
    float* out = (float*)d_out;

    cudaFuncSetAttribute(nam_main, cudaFuncAttributeMaxDynamicSharedMemorySize,
                         SMEM_BYTES);

    const int zero_blocks = (out_size + THREADS - 1) / THREADS;
    nam_setup<<<3 * F_SZ + F_SZ * T_SZ + zero_blocks, THREADS>>>(
        out, out_size, W2, W3, W4, Wh1, bh1, Wh2, bh2);

    dim3 grid(B_SZ / TB, F_SZ / FG);
    nam_main<<<grid, THREADS, SMEM_BYTES>>>(x, a, W1, b1, b2, b3, b4, out);
}

// round 7
// speedup vs baseline: 3.8545x; 1.0054x over previous
#include <cuda_runtime.h>
#include <cuda_bf16.h>
#include <cstdint>

// Problem constants
#define B_SZ   4096
#define F_SZ   100
#define H_SZ   128
#define H2_SZ  64
#define T_SZ   2

// Tiling: 2 independent 128-thread groups per CTA; each group: 64 rows x 5 features
#define TB      64      // batch rows per CTA (shared by both groups)
#define FG      5       // features per GROUP
#define THREADS 256
#define GT      128     // threads per group
#define WB32    8192    // uint32 entries per packed 32KB weight matrix

// Fragment-packed bf16 split weights: [layer][f][hi/lo][8192] uint32 (bf16x2)
__device__ uint32_t g_wp[3][F_SZ][2][WB32];
// Collapsed head
__device__ float g_wv[F_SZ * T_SZ * H_SZ];
__device__ float g_c[F_SZ * T_SZ];

// ---------------- scalar helpers ----------------
__device__ __forceinline__ float elu_f(float v) {
    return v > 0.0f ? v : (__expf(v) - 1.0f);
}
__device__ __forceinline__ uint32_t pack_split(float v0, float v1, float& r0, float& r1) {
    uint32_t p;
    asm("cvt.rn.bf16x2.f32 %0, %1, %2;" : "=r"(p) : "f"(v1), "f"(v0));
    float f0, f1;
    asm("{.reg .b16 l,h; mov.b32 {l,h}, %2; cvt.f32.bf16 %0, l; cvt.f32.bf16 %1, h;}"
        : "=f"(f0), "=f"(f1) : "r"(p));
    r0 = v0 - f0; r1 = v1 - f1;
    return p;
}
__device__ __forceinline__ uint32_t pack2bf(float v0, float v1) {
    uint32_t p;
    asm("cvt.rn.bf16x2.f32 %0, %1, %2;" : "=r"(p) : "f"(v1), "f"(v0));
    return p;
}

// mma.sync m16n8k16 bf16 (baseline PTX, works under compute_103)
__device__ __forceinline__ void mma16816(float d[4], const uint32_t a[4],
                                         uint32_t b0, uint32_t b1) {
    asm("mma.sync.aligned.m16n8k16.row.col.f32.bf16.bf16.f32 "
        "{%0,%1,%2,%3}, {%4,%5,%6,%7}, {%8,%9}, {%0,%1,%2,%3};"
        : "+f"(d[0]), "+f"(d[1]), "+f"(d[2]), "+f"(d[3])
        : "r"(a[0]), "r"(a[1]), "r"(a[2]), "r"(a[3]), "r"(b0), "r"(b1));
}

// ---------------- cp.async ----------------
__device__ __forceinline__ void cp16(uint32_t saddr, const void* g) {
    asm volatile("cp.async.cg.shared.global [%0], [%1], 16;\n" :: "r"(saddr), "l"(g));
}
__device__ __forceinline__ void cp_commit() {
    asm volatile("cp.async.commit_group;\n" ::: "memory");
}
__device__ __forceinline__ void cp_wait0() {
    asm volatile("cp.async.wait_group 0;\n" ::: "memory");
}
// copy one 64KB packed weight block (hi 32KB + lo 32KB) with 128 threads
__device__ __forceinline__ void issue_w(uint32_t sdst, const char* gsrc, int gt) {
#pragma unroll
    for (int i = 0; i < 32; i++) {
        int b = (gt + i * GT) * 16;
        cp16(sdst + b, gsrc + b);
    }
    cp_commit();
}

// ---------------- setup: pack weights, head collapse, zero out ----------------
__global__ void nam_setup(float* __restrict__ out, int n_out,
                          const float* __restrict__ W2, const float* __restrict__ W3,
                          const float* __restrict__ W4,
                          const float* __restrict__ Wh1, const float* __restrict__ bh1,
                          const float* __restrict__ Wh2, const float* __restrict__ bh2) {
    const int blk = blockIdx.x;
    const int tid = threadIdx.x;
    if (blk < 3 * F_SZ) {
        const int l = blk / F_SZ, f = blk % F_SZ;
        const float* W = (l == 0 ? W2 : (l == 1 ? W3 : W4)) + (long)f * H_SZ * H_SZ;
        uint32_t* hi = &g_wp[l][f][0][0];
        uint32_t* lo = &g_wp[l][f][1][0];
        for (int e = tid; e < 4096; e += THREADS) {
            const int lane = e & 31;
            const int t = lane & 3, g = lane >> 2;
            const int nt = (e >> 5) & 15, ks = e >> 9;
            const int n = nt * 8 + g;
            const int k0 = ks * 16 + t * 2;
            float w00 = W[(k0)     * H_SZ + n];
            float w01 = W[(k0 + 1) * H_SZ + n];
            float w10 = W[(k0 + 8) * H_SZ + n];
            float w11 = W[(k0 + 9) * H_SZ + n];
            float r00, r01, r10, r11;
            uint32_t h0 = pack_split(w00, w01, r00, r01);
            uint32_t h1 = pack_split(w10, w11, r10, r11);
            hi[2 * e]     = h0;
            hi[2 * e + 1] = h1;
            lo[2 * e]     = pack2bf(r00, r01);
            lo[2 * e + 1] = pack2bf(r10, r11);
        }
    } else if (blk < 3 * F_SZ + F_SZ * T_SZ) {
        const int ft = blk - 3 * F_SZ;
        __shared__ float s2[H2_SZ];
        if (tid < H2_SZ) s2[tid] = Wh2[ft * H2_SZ + tid];
        __syncthreads();
        if (tid < H_SZ) {
            const float* wp = Wh1 + ((long)ft * H_SZ + tid) * H2_SZ;
            float s = 0.0f;
#pragma unroll 8
            for (int m = 0; m < H2_SZ; m++) s += wp[m] * s2[m];
            g_wv[ft * H_SZ + tid] = s;
            if (tid == 0) {
                float cc = bh2[ft];
                const float* bp = bh1 + ft * H2_SZ;
                for (int m = 0; m < H2_SZ; m++) cc += bp[m] * s2[m];
                g_c[ft] = cc;
            }
        }
    } else {
        int i = (blk - (3 * F_SZ + F_SZ * T_SZ)) * THREADS + tid;
        if (i < n_out) out[i] = 0.0f;
    }
}

// ---------------- fused main kernel ----------------
// smem: [0,64K) group0 Wbuf, [64K,128K) group1 Wbuf, then 2 x 1024-float areas
#define FS_OFF  131072
#define GF      1024     // floats of small area per group
#define SX_I    0        // 64
#define SW1_I   64       // 128
#define SB1_I   192      // 128
#define SBIAS_I 320      // 384 (b2|b3|b4)
#define SWV_I   704      // 256
#define SC_I    960      // 2
#define SMEM_BYTES (FS_OFF + 2 * GF * 4)

#define GBAR() asm volatile("bar.sync %0, 128;" :: "r"(gid + 1) : "memory")

__global__ void __launch_bounds__(THREADS, 1)
nam_main(const float* __restrict__ x, const int* __restrict__ a,
         const float* __restrict__ W1, const float* __restrict__ b1,
         const float* __restrict__ b2, const float* __restrict__ b3,
         const float* __restrict__ b4, float* __restrict__ out) {
    extern __shared__ char smem[];

    const int tid = threadIdx.x;
    const int gid = tid >> 7;        // group 0/1
    const int gt  = tid & 127;       // thread within group
    const int w4 = gt >> 5, lane = gt & 31;
    const int t = lane & 3, g = lane >> 2;
    const int t2 = t * 2;
    const int lr0 = 16 * w4 + g;     // local row (acc c0/c1), 0..63
    const int lr1 = lr0 + 8;
    const int b0 = blockIdx.x * TB;
    const int fbase = blockIdx.y * (2 * FG) + gid * FG;
    const int grow0 = b0 + lr0, grow1 = b0 + lr1;

    float* fs  = (float*)(smem + FS_OFF) + gid * GF;
    float* sx    = fs + SX_I;
    float* sw1   = fs + SW1_I;
    float* sb1   = fs + SB1_I;
    float* sbias = fs + SBIAS_I;
    float* swv   = fs + SWV_I;
    float* sc    = fs + SC_I;

    const uint32_t smem_u32 = (uint32_t)__cvta_generic_to_shared(smem);
    const uint32_t wbase = smem_u32 + (uint32_t)gid * 65536u;
    const uint32_t* const Wh = (const uint32_t*)(smem + gid * 65536);
    const uint32_t* const Wl = Wh + WB32;

    const int t0 = a[grow0], t1 = a[grow1];
    const int t0w = t0 * H_SZ, t1w = t1 * H_SZ;

    float acc[16][4];
    uint32_t Ah[8][4], Al[8][4];
    float bbs[16][4];
#pragma unroll
    for (int nt = 0; nt < 16; nt++)
#pragma unroll
        for (int j = 0; j < 4; j++) bbs[nt][j] = 0.0f;
    float yacc0 = 0.0f, yacc1 = 0.0f;

    // prologue: this group's first weight block
    issue_w(wbase, (const char*)&g_wp[0][fbase][0][0], gt);

    for (int ff = 0; ff < FG; ff++) {
        const int f = fbase + ff;
        GBAR();   // prev feature consumers done with small buffers
        if (gt < TB) sx[gt] = x[(long)(b0 + gt) * F_SZ + f];
        sw1[gt]         = W1[f * H_SZ + gt];
        sb1[gt]         = b1[f * H_SZ + gt];
        sbias[gt]       = b2[f * H_SZ + gt];
        sbias[128 + gt] = b3[f * H_SZ + gt];
        sbias[256 + gt] = b4[f * H_SZ + gt];
        swv[gt]       = g_wv[f * 256 + gt];
        swv[128 + gt] = g_wv[f * 256 + 128 + gt];
        if (gt < 2) sc[gt] = g_c[f * 2 + gt];
        GBAR();

        // ---- layer 1: build A-fragments directly (hi/lo bf16 split) ----
        {
            const float xv0 = sx[lr0], xv1 = sx[lr1];
#pragma unroll
            for (int kk = 0; kk < 8; kk++) {
                const int cA = 16 * kk + t2, cB = cA + 8;
                float2 wA = *(const float2*)&sw1[cA];
                float2 bA = *(const float2*)&sb1[cA];
                float2 wB = *(const float2*)&sw1[cB];
                float2 bB = *(const float2*)&sb1[cB];
                float r0, r1;
                float v0 = elu_f(xv0 * wA.x + bA.x);
                float v1 = elu_f(xv0 * wA.y + bA.y);
                Ah[kk][0] = pack_split(v0, v1, r0, r1); Al[kk][0] = pack2bf(r0, r1);
                v0 = elu_f(xv1 * wA.x + bA.x);
                v1 = elu_f(xv1 * wA.y + bA.y);
                Ah[kk][1] = pack_split(v0, v1, r0, r1); Al[kk][1] = pack2bf(r0, r1);
                v0 = elu_f(xv0 * wB.x + bB.x);
                v1 = elu_f(xv0 * wB.y + bB.y);
                Ah[kk][2] = pack_split(v0, v1, r0, r1); Al[kk][2] = pack2bf(r0, r1);
                v0 = elu_f(xv1 * wB.x + bB.x);
                v1 = elu_f(xv1 * wB.y + bB.y);
                Ah[kk][3] = pack_split(v0, v1, r0, r1); Al[kk][3] = pack2bf(r0, r1);
            }
        }

#pragma unroll 1
        for (int l = 0; l < 3; l++) {
            cp_wait0();
            GBAR();   // this group's weight block ready & visible

            // ---- 3-pass split GEMM ----
#pragma unroll
            for (int nt = 0; nt < 16; nt++) {
                acc[nt][0] = 0.f; acc[nt][1] = 0.f;
                acc[nt][2] = 0.f; acc[nt][3] = 0.f;
            }
#pragma unroll
            for (int ks = 0; ks < 8; ks++) {
                const uint32_t* bh = Wh + ks * 1024 + lane * 2;
                const uint32_t* bl = Wl + ks * 1024 + lane * 2;
#pragma unroll
                for (int nt = 0; nt < 16; nt++) {
                    uint2 wh = *(const uint2*)(bh + nt * 64);
                    uint2 wl = *(const uint2*)(bl + nt * 64);
                    mma16816(acc[nt], Ah[ks], wh.x, wh.y);
                    mma16816(acc[nt], Al[ks], wh.x, wh.y);
                    mma16816(acc[nt], Ah[ks], wl.x, wl.y);
                }
            }

            GBAR();   // all group threads done reading the weight buffer

            // prefetch next weight block into the (single) buffer
            const char* nxt = (l < 2) ? (const char*)&g_wp[l + 1][f][0][0]
                              : ((ff + 1 < FG) ? (const char*)&g_wp[0][f + 1][0][0]
                                               : nullptr);
            if (nxt) issue_w(wbase, nxt, gt);

            if (l < 2) {
                // ---- epilogue: bias + ELU + split -> next layer's A frags ----
                const float* sb = sbias + l * 128;
#pragma unroll
                for (int kk = 0; kk < 8; kk++) {
                    const int nt0 = 2 * kk, nt1 = 2 * kk + 1;
                    float2 bA = *(const float2*)&sb[8 * nt0 + t2];
                    float2 bB = *(const float2*)&sb[8 * nt1 + t2];
                    float r0, r1;
                    float v0 = elu_f(acc[nt0][0] + bA.x);
                    float v1 = elu_f(acc[nt0][1] + bA.y);
                    Ah[kk][0] = pack_split(v0, v1, r0, r1); Al[kk][0] = pack2bf(r0, r1);
                    v0 = elu_f(acc[nt0][2] + bA.x);
                    v1 = elu_f(acc[nt0][3] + bA.y);
                    Ah[kk][1] = pack_split(v0, v1, r0, r1); Al[kk][1] = pack2bf(r0, r1);
                    v0 = elu_f(acc[nt1][0] + bB.x);
                    v1 = elu_f(acc[nt1][1] + bB.y);
                    Ah[kk][2] = pack_split(v0, v1, r0, r1); Al[kk][2] = pack2bf(r0, r1);
                    v0 = elu_f(acc[nt1][2] + bB.x);
                    v1 = elu_f(acc[nt1][3] + bB.y);
                    Ah[kk][3] = pack_split(v0, v1, r0, r1); Al[kk][3] = pack2bf(r0, r1);
                }
            } else {
                // ---- layer-4 epilogue: bb accumulate + collapsed head ----
                const float* sb4 = sbias + 256;
                float y0 = 0.0f, y1 = 0.0f;
#pragma unroll
                for (int nt = 0; nt < 16; nt++) {
                    float2 b4v = *(const float2*)&sb4[8 * nt + t2];
                    float bb0 = acc[nt][0] + b4v.x;
                    float bb1 = acc[nt][1] + b4v.y;
                    float bb2 = acc[nt][2] + b4v.x;
                    float bb3 = acc[nt][3] + b4v.y;
                    bbs[nt][0] += bb0; bbs[nt][1] += bb1;
                    bbs[nt][2] += bb2; bbs[nt][3] += bb3;
                    float2 wv0 = *(const float2*)&swv[t0w + 8 * nt + t2];
                    float2 wv1 = *(const float2*)&swv[t1w + 8 * nt + t2];
                    y0 += bb0 * wv0.x + bb1 * wv0.y;
                    y1 += bb2 * wv1.x + bb3 * wv1.y;
                }
                if (t == 0) { y0 += sc[t0]; y1 += sc[t1]; }
                yacc0 += y0; yacc1 += y1;
            }
        }
    }

    // ---- finale: atomics into output ----
#pragma unroll
    for (int nt = 0; nt < 16; nt++) {
        const int col = 8 * nt + t2;
        atomicAdd(&out[(long)grow0 * H_SZ + col],     bbs[nt][0]);
        atomicAdd(&out[(long)grow0 * H_SZ + col + 1], bbs[nt][1]);
        atomicAdd(&out[(long)grow1 * H_SZ + col],     bbs[nt][2]);
        atomicAdd(&out[(long)grow1 * H_SZ + col + 1], bbs[nt][3]);
    }
    yacc0 += __shfl_xor_sync(0xffffffffu, yacc0, 1);
    yacc0 += __shfl_xor_sync(0xffffffffu, yacc0, 2);
    yacc1 += __shfl_xor_sync(0xffffffffu, yacc1, 1);
    yacc1 += __shfl_xor_sync(0xffffffffu, yacc1, 2);
    if (t == 0) {
        atomicAdd(&out[B_SZ * H_SZ + grow0], yacc0);
        atomicAdd(&out[B_SZ * H_SZ + grow1], yacc1);
    }
}

// ---------------- launch ----------------
extern "C" void kernel_launch(void* const* d_in, const int* in_sizes, int n_in,
                              void* d_out, int out_size) {
    const float* x   = (const float*)d_in[0];
    const int*   a   = (const int*)d_in[1];
    const float* W1  = (const float*)d_in[2];
    const float* b1  = (const float*)d_in[3];
    const float* W2  = (const float*)d_in[4];
    const float* b2  = (const float*)d_in[5];
    const float* W3  = (const float*)d_in[6];
    const float* b3  = (const float*)d_in[7];
    const float* W4  = (const float*)d_in[8];
    const float* b4  = (const float*)d_in[9];
    const float* Wh1 = (const float*)d_in[10];
    const float* bh1 = (const float*)d_in[11];
    const float* Wh2 = (const float*)d_in[12];
    const float* bh2 = (const float*)d_in[13];
    float* out = (float*)d_out;

    cudaFuncSetAttribute(nam_main, cudaFuncAttributeMaxDynamicSharedMemorySize,
                         SMEM_BYTES);

    const int zero_blocks = (out_size + THREADS - 1) / THREADS;
    nam_setup<<<3 * F_SZ + F_SZ * T_SZ + zero_blocks, THREADS>>>(
        out, out_size, W2, W3, W4, Wh1, bh1, Wh2, bh2);

    dim3 grid(B_SZ / TB, F_SZ / (2 * FG));
    nam_main<<<grid, THREADS, SMEM_BYTES>>>(x, a, W1, b1, b2, b3, b4, out);
}

// round 8
// speedup vs baseline: 5.4311x; 1.4090x over previous
#include <cuda_runtime.h>
#include <cuda_fp16.h>
#include <cstdint>

// Problem constants
#define B_SZ   4096
#define F_SZ   100
#define H_SZ   128
#define H2_SZ  64
#define T_SZ   2

// Tiling: 2 independent 128-thread groups per CTA; each group: 64 rows x 5 features
#define TB      64      // batch rows per CTA (shared by both groups)
#define FG      5       // features per GROUP
#define NSTEP   (3 * FG)
#define THREADS 256
#define GT      128     // threads per group
#define WB32    8192    // uint32 entries per packed 32KB fp16 weight matrix

// Fragment-packed fp16 weights: [layer][f][8192] uint32 (f16x2)
// entry e = ((ks*16 + nt)*32 + lane); regs at 2e, 2e+1
__device__ uint32_t g_wp[3][F_SZ][WB32];
// Collapsed head
__device__ float g_wv[F_SZ * T_SZ * H_SZ];
__device__ float g_c[F_SZ * T_SZ];

// ---------------- scalar helpers ----------------
__device__ __forceinline__ float elu_f(float v) {
    return v > 0.0f ? v : (__expf(v) - 1.0f);
}
// pack two fp32 into f16x2 (low half = v0), return fp32 residuals
__device__ __forceinline__ uint32_t pack_split(float v0, float v1, float& r0, float& r1) {
    uint32_t p;
    asm("cvt.rn.f16x2.f32 %0, %1, %2;" : "=r"(p) : "f"(v1), "f"(v0));
    float f0, f1;
    asm("{.reg .b16 l,h; mov.b32 {l,h}, %2; cvt.f32.f16 %0, l; cvt.f32.f16 %1, h;}"
        : "=f"(f0), "=f"(f1) : "r"(p));
    r0 = v0 - f0; r1 = v1 - f1;
    return p;
}
__device__ __forceinline__ uint32_t pack2h(float v0, float v1) {
    uint32_t p;
    asm("cvt.rn.f16x2.f32 %0, %1, %2;" : "=r"(p) : "f"(v1), "f"(v0));
    return p;
}

// mma.sync m16n8k16 fp16 -> fp32 (baseline PTX, compiles under compute_103)
__device__ __forceinline__ void mma16816(float d[4], const uint32_t a[4],
                                         uint32_t b0, uint32_t b1) {
    asm("mma.sync.aligned.m16n8k16.row.col.f32.f16.f16.f32 "
        "{%0,%1,%2,%3}, {%4,%5,%6,%7}, {%8,%9}, {%0,%1,%2,%3};"
        : "+f"(d[0]), "+f"(d[1]), "+f"(d[2]), "+f"(d[3])
        : "r"(a[0]), "r"(a[1]), "r"(a[2]), "r"(a[3]), "r"(b0), "r"(b1));
}

// ---------------- cp.async ----------------
__device__ __forceinline__ void cp16(uint32_t saddr, const void* g) {
    asm volatile("cp.async.cg.shared.global [%0], [%1], 16;\n" :: "r"(saddr), "l"(g));
}
__device__ __forceinline__ void cp_commit() {
    asm volatile("cp.async.commit_group;\n" ::: "memory");
}
__device__ __forceinline__ void cp_wait0() {
    asm volatile("cp.async.wait_group 0;\n" ::: "memory");
}
__device__ __forceinline__ void cp_wait1() {
    asm volatile("cp.async.wait_group 1;\n" ::: "memory");
}
// copy one 32KB packed weight matrix with 128 threads (16 x 16B per thread)
__device__ __forceinline__ void issue_w(uint32_t sdst, const char* gsrc, int gt) {
#pragma unroll
    for (int i = 0; i < 16; i++) {
        int b = (gt + i * GT) * 16;
        cp16(sdst + b, gsrc + b);
    }
    cp_commit();
}

// ---------------- setup: pack weights, head collapse, zero out ----------------
__global__ void nam_setup(float* __restrict__ out, int n_out,
                          const float* __restrict__ W2, const float* __restrict__ W3,
                          const float* __restrict__ W4,
                          const float* __restrict__ Wh1, const float* __restrict__ bh1,
                          const float* __restrict__ Wh2, const float* __restrict__ bh2) {
    const int blk = blockIdx.x;
    const int tid = threadIdx.x;
    if (blk < 3 * F_SZ) {
        const int l = blk / F_SZ, f = blk % F_SZ;
        const float* W = (l == 0 ? W2 : (l == 1 ? W3 : W4)) + (long)f * H_SZ * H_SZ;
        uint32_t* hi = &g_wp[l][f][0];
        for (int e = tid; e < 4096; e += THREADS) {
            const int lane = e & 31;
            const int t = lane & 3, g = lane >> 2;
            const int nt = (e >> 5) & 15, ks = e >> 9;
            const int n = nt * 8 + g;
            const int k0 = ks * 16 + t * 2;
            float w00 = W[(k0)     * H_SZ + n];
            float w01 = W[(k0 + 1) * H_SZ + n];
            float w10 = W[(k0 + 8) * H_SZ + n];
            float w11 = W[(k0 + 9) * H_SZ + n];
            hi[2 * e]     = pack2h(w00, w01);
            hi[2 * e + 1] = pack2h(w10, w11);
        }
    } else if (blk < 3 * F_SZ + F_SZ * T_SZ) {
        const int ft = blk - 3 * F_SZ;
        __shared__ float s2[H2_SZ];
        if (tid < H2_SZ) s2[tid] = Wh2[ft * H2_SZ + tid];
        __syncthreads();
        if (tid < H_SZ) {
            const float* wp = Wh1 + ((long)ft * H_SZ + tid) * H2_SZ;
            float s = 0.0f;
#pragma unroll 8
            for (int m = 0; m < H2_SZ; m++) s += wp[m] * s2[m];
            g_wv[ft * H_SZ + tid] = s;
            if (tid == 0) {
                float cc = bh2[ft];
                const float* bp = bh1 + ft * H2_SZ;
                for (int m = 0; m < H2_SZ; m++) cc += bp[m] * s2[m];
                g_c[ft] = cc;
            }
        }
    } else {
        int i = (blk - (3 * F_SZ + F_SZ * T_SZ)) * THREADS + tid;
        if (i < n_out) out[i] = 0.0f;
    }
}

// ---------------- fused main kernel ----------------
// smem: [0,32K) g0 buf0, [32K,64K) g0 buf1, [64K,96K) g1 buf0, [96K,128K) g1 buf1
#define FS_OFF  131072
#define GF      1024     // floats of small area per group
#define SX_I    0        // 64
#define SW1_I   64       // 128
#define SB1_I   192      // 128
#define SBIAS_I 320      // 384 (b2|b3|b4)
#define SWV_I   704      // 256
#define SC_I    960      // 2
#define SMEM_BYTES (FS_OFF + 2 * GF * 4)

#define GBAR() asm volatile("bar.sync %0, 128;" :: "r"(gid + 1) : "memory")

__global__ void __launch_bounds__(THREADS, 1)
nam_main(const float* __restrict__ x, const int* __restrict__ a,
         const float* __restrict__ W1, const float* __restrict__ b1,
         const float* __restrict__ b2, const float* __restrict__ b3,
         const float* __restrict__ b4, float* __restrict__ out) {
    extern __shared__ char smem[];

    const int tid = threadIdx.x;
    const int gid = tid >> 7;        // group 0/1
    const int gt  = tid & 127;       // thread within group
    const int w4 = gt >> 5, lane = gt & 31;
    const int t = lane & 3, g = lane >> 2;
    const int t2 = t * 2;
    const int lr0 = 16 * w4 + g;     // local row (acc c0/c1), 0..63
    const int lr1 = lr0 + 8;
    const int b0 = blockIdx.x * TB;
    const int fbase = blockIdx.y * (2 * FG) + gid * FG;
    const int grow0 = b0 + lr0, grow1 = b0 + lr1;

    float* fs  = (float*)(smem + FS_OFF) + gid * GF;
    float* sx    = fs + SX_I;
    float* sw1   = fs + SW1_I;
    float* sb1   = fs + SB1_I;
    float* sbias = fs + SBIAS_I;
    float* swv   = fs + SWV_I;
    float* sc    = fs + SC_I;

    const uint32_t smem_u32 = (uint32_t)__cvta_generic_to_shared(smem);
    const uint32_t wgbase = smem_u32 + (uint32_t)gid * 65536u;
    const char* const wgen = smem + gid * 65536;

    const int t0 = a[grow0], t1 = a[grow1];
    const int t0w = t0 * H_SZ, t1w = t1 * H_SZ;

    float acc[16][4];
    uint32_t Ah[8][4], Al[8][4];
    float bbs[16][4];
#pragma unroll
    for (int nt = 0; nt < 16; nt++)
#pragma unroll
        for (int j = 0; j < 4; j++) bbs[nt][j] = 0.0f;
    float yacc0 = 0.0f, yacc1 = 0.0f;

    // prologue: steps 0 and 1 (feature fbase, layers W2 and W3)
    issue_w(wgbase,          (const char*)&g_wp[0][fbase][0], gt);
    issue_w(wgbase + 32768u, (const char*)&g_wp[1][fbase][0], gt);

    for (int ff = 0; ff < FG; ff++) {
        const int f = fbase + ff;
        GBAR();   // prev feature consumers done with small buffers
        if (gt < TB) sx[gt] = x[(long)(b0 + gt) * F_SZ + f];
        sw1[gt]         = W1[f * H_SZ + gt];
        sb1[gt]         = b1[f * H_SZ + gt];
        sbias[gt]       = b2[f * H_SZ + gt];
        sbias[128 + gt] = b3[f * H_SZ + gt];
        sbias[256 + gt] = b4[f * H_SZ + gt];
        swv[gt]       = g_wv[f * 256 + gt];
        swv[128 + gt] = g_wv[f * 256 + 128 + gt];
        if (gt < 2) sc[gt] = g_c[f * 2 + gt];
        GBAR();

        // ---- layer 1: build A-fragments directly (hi/lo fp16 split) ----
        {
            const float xv0 = sx[lr0], xv1 = sx[lr1];
#pragma unroll
            for (int kk = 0; kk < 8; kk++) {
                const int cA = 16 * kk + t2, cB = cA + 8;
                float2 wA = *(const float2*)&sw1[cA];
                float2 bA = *(const float2*)&sb1[cA];
                float2 wB = *(const float2*)&sw1[cB];
                float2 bB = *(const float2*)&sb1[cB];
                float r0, r1;
                float v0 = elu_f(xv0 * wA.x + bA.x);
                float v1 = elu_f(xv0 * wA.y + bA.y);
                Ah[kk][0] = pack_split(v0, v1, r0, r1); Al[kk][0] = pack2h(r0, r1);
                v0 = elu_f(xv1 * wA.x + bA.x);
                v1 = elu_f(xv1 * wA.y + bA.y);
                Ah[kk][1] = pack_split(v0, v1, r0, r1); Al[kk][1] = pack2h(r0, r1);
                v0 = elu_f(xv0 * wB.x + bB.x);
                v1 = elu_f(xv0 * wB.y + bB.y);
                Ah[kk][2] = pack_split(v0, v1, r0, r1); Al[kk][2] = pack2h(r0, r1);
                v0 = elu_f(xv1 * wB.x + bB.x);
                v1 = elu_f(xv1 * wB.y + bB.y);
                Ah[kk][3] = pack_split(v0, v1, r0, r1); Al[kk][3] = pack2h(r0, r1);
            }
        }

#pragma unroll 1
        for (int l = 0; l < 3; l++) {
            const int step = ff * 3 + l;
            if (step == NSTEP - 1) cp_wait0(); else cp_wait1();
            GBAR();   // this step's weight buffer ready & visible to group

            const uint32_t* Wh =
                (const uint32_t*)(wgen + (step & 1) * 32768);

            // ---- 2-pass split GEMM (Ah*Wh + Al*Wh), shared B fragments ----
#pragma unroll
            for (int nt = 0; nt < 16; nt++) {
                acc[nt][0] = 0.f; acc[nt][1] = 0.f;
                acc[nt][2] = 0.f; acc[nt][3] = 0.f;
            }
#pragma unroll
            for (int ks = 0; ks < 8; ks++) {
                const uint32_t* bh = Wh + ks * 1024 + lane * 2;
#pragma unroll
                for (int nt = 0; nt < 16; nt++) {
                    uint2 wh = *(const uint2*)(bh + nt * 64);
                    mma16816(acc[nt], Ah[ks], wh.x, wh.y);
                    mma16816(acc[nt], Al[ks], wh.x, wh.y);
                }
            }

            GBAR();   // all group threads done reading this weight buffer

            // prefetch step+2 into the buffer just released
            const int s2 = step + 2;
            if (s2 < NSTEP)
                issue_w(wgbase + (uint32_t)(step & 1) * 32768u,
                        (const char*)&g_wp[s2 % 3][fbase + s2 / 3][0], gt);

            if (l < 2) {
                // ---- epilogue: bias + ELU + split -> next layer's A frags ----
                const float* sb = sbias + l * 128;
#pragma unroll
                for (int kk = 0; kk < 8; kk++) {
                    const int nt0 = 2 * kk, nt1 = 2 * kk + 1;
                    float2 bA = *(const float2*)&sb[8 * nt0 + t2];
                    float2 bB = *(const float2*)&sb[8 * nt1 + t2];
                    float r0, r1;
                    float v0 = elu_f(acc[nt0][0] + bA.x);
                    float v1 = elu_f(acc[nt0][1] + bA.y);
                    Ah[kk][0] = pack_split(v0, v1, r0, r1); Al[kk][0] = pack2h(r0, r1);
                    v0 = elu_f(acc[nt0][2] + bA.x);
                    v1 = elu_f(acc[nt0][3] + bA.y);
                    Ah[kk][1] = pack_split(v0, v1, r0, r1); Al[kk][1] = pack2h(r0, r1);
                    v0 = elu_f(acc[nt1][0] + bB.x);
                    v1 = elu_f(acc[nt1][1] + bB.y);
                    Ah[kk][2] = pack_split(v0, v1, r0, r1); Al[kk][2] = pack2h(r0, r1);
                    v0 = elu_f(acc[nt1][2] + bB.x);
                    v1 = elu_f(acc[nt1][3] + bB.y);
                    Ah[kk][3] = pack_split(v0, v1, r0, r1); Al[kk][3] = pack2h(r0, r1);
                }
            } else {
                // ---- layer-4 epilogue: bb accumulate + collapsed head ----
                const float* sb4 = sbias + 256;
                float y0 = 0.0f, y1 = 0.0f;
#pragma unroll
                for (int nt = 0; nt < 16; nt++) {
                    float2 b4v = *(const float2*)&sb4[8 * nt + t2];
                    float bb0 = acc[nt][0] + b4v.x;
                    float bb1 = acc[nt][1] + b4v.y;
                    float bb2 = acc[nt][2] + b4v.x;
                    float bb3 = acc[nt][3] + b4v.y;
                    bbs[nt][0] += bb0; bbs[nt][1] += bb1;
                    bbs[nt][2] += bb2; bbs[nt][3] += bb3;
                    float2 wv0 = *(const float2*)&swv[t0w + 8 * nt + t2];
                    float2 wv1 = *(const float2*)&swv[t1w + 8 * nt + t2];
                    y0 += bb0 * wv0.x + bb1 * wv0.y;
                    y1 += bb2 * wv1.x + bb3 * wv1.y;
                }
                if (t == 0) { y0 += sc[t0]; y1 += sc[t1]; }
                yacc0 += y0; yacc1 += y1;
            }
        }
    }

    // ---- finale: atomics into output ----
#pragma unroll
    for (int nt = 0; nt < 16; nt++) {
        const int col = 8 * nt + t2;
        atomicAdd(&out[(long)grow0 * H_SZ + col],     bbs[nt][0]);
        atomicAdd(&out[(long)grow0 * H_SZ + col + 1], bbs[nt][1]);
        atomicAdd(&out[(long)grow1 * H_SZ + col],     bbs[nt][2]);
        atomicAdd(&out[(long)grow1 * H_SZ + col + 1], bbs[nt][3]);
    }
    yacc0 += __shfl_xor_sync(0xffffffffu, yacc0, 1);
    yacc0 += __shfl_xor_sync(0xffffffffu, yacc0, 2);
    yacc1 += __shfl_xor_sync(0xffffffffu, yacc1, 1);
    yacc1 += __shfl_xor_sync(0xffffffffu, yacc1, 2);
    if (t == 0) {
        atomicAdd(&out[B_SZ * H_SZ + grow0], yacc0);
        atomicAdd(&out[B_SZ * H_SZ + grow1], yacc1);
    }
}

// ---------------- launch ----------------
extern "C" void kernel_launch(void* const* d_in, const int* in_sizes, int n_in,
                              void* d_out, int out_size) {
    const float* x   = (const float*)d_in[0];
    const int*   a   = (const int*)d_in[1];
    const float* W1  = (const float*)d_in[2];
    const float* b1  = (const float*)d_in[3];
    const float* W2  = (const float*)d_in[4];
    const float* b2  = (const float*)d_in[5];
    const float* W3  = (const float*)d_in[6];
    const float* b3  = (const float*)d_in[7];
    const float* W4  = (const float*)d_in[8];
    const float* b4  = (const float*)d_in[9];
    const float* Wh1 = (const float*)d_in[10];
    const float* bh1 = (const float*)d_in[11];
    const float* Wh2 = (const float*)d_in[12];
    const float* bh2 = (const float*)d_in[13];
    float* out = (float*)d_out;

    cudaFuncSetAttribute(nam_main, cudaFuncAttributeMaxDynamicSharedMemorySize,
                         SMEM_BYTES);

    const int zero_blocks = (out_size + THREADS - 1) / THREADS;
    nam_setup<<<3 * F_SZ + F_SZ * T_SZ + zero_blocks, THREADS>>>(
        out, out_size, W2, W3, W4, Wh1, bh1, Wh2, bh2);

    dim3 grid(B_SZ / TB, F_SZ / (2 * FG));
    nam_main<<<grid, THREADS, SMEM_BYTES>>>(x, a, W1, b1, b2, b3, b4, out);
}

// round 9
// speedup vs baseline: 5.6174x; 1.0343x over previous
#include <cuda_runtime.h>
#include <cuda_fp16.h>
#include <cstdint>

// Problem constants
#define B_SZ   4096
#define F_SZ   100
#define H_SZ   128
#define H2_SZ  64
#define T_SZ   2

// Tiling: 2 independent 128-thread groups per CTA; each group: 64 rows x FG features
#define TB      64      // batch rows per CTA (shared by both groups)
#define FG      2       // features per GROUP
#define NSTEP   (3 * FG)
#define THREADS 256
#define GT      128     // threads per group
#define WB32    8192    // uint32 entries per packed 32KB fp16 weight matrix
#define SKEW_CYC 4096   // group-1 start skew (~half a layer period)

// Fragment-packed fp16 weights: [layer][f][8192] uint32 (f16x2)
// entry e = ((ks*16 + nt)*32 + lane); regs at 2e, 2e+1
__device__ uint32_t g_wp[3][F_SZ][WB32];
// Collapsed head
__device__ float g_wv[F_SZ * T_SZ * H_SZ];
__device__ float g_c[F_SZ * T_SZ];

// ---------------- scalar helpers ----------------
__device__ __forceinline__ float elu_f(float v) {
    return v > 0.0f ? v : (__expf(v) - 1.0f);
}
// pack two fp32 into f16x2 (low half = v0), return fp32 residuals
__device__ __forceinline__ uint32_t pack_split(float v0, float v1, float& r0, float& r1) {
    uint32_t p;
    asm("cvt.rn.f16x2.f32 %0, %1, %2;" : "=r"(p) : "f"(v1), "f"(v0));
    float f0, f1;
    asm("{.reg .b16 l,h; mov.b32 {l,h}, %2; cvt.f32.f16 %0, l; cvt.f32.f16 %1, h;}"
        : "=f"(f0), "=f"(f1) : "r"(p));
    r0 = v0 - f0; r1 = v1 - f1;
    return p;
}
__device__ __forceinline__ uint32_t pack2h(float v0, float v1) {
    uint32_t p;
    asm("cvt.rn.f16x2.f32 %0, %1, %2;" : "=r"(p) : "f"(v1), "f"(v0));
    return p;
}

// mma.sync m16n8k16 fp16 -> fp32 (baseline PTX, compiles under compute_103)
__device__ __forceinline__ void mma16816(float d[4], const uint32_t a[4],
                                         uint32_t b0, uint32_t b1) {
    asm("mma.sync.aligned.m16n8k16.row.col.f32.f16.f16.f32 "
        "{%0,%1,%2,%3}, {%4,%5,%6,%7}, {%8,%9}, {%0,%1,%2,%3};"
        : "+f"(d[0]), "+f"(d[1]), "+f"(d[2]), "+f"(d[3])
        : "r"(a[0]), "r"(a[1]), "r"(a[2]), "r"(a[3]), "r"(b0), "r"(b1));
}

// ---------------- cp.async ----------------
__device__ __forceinline__ void cp16(uint32_t saddr, const void* g) {
    asm volatile("cp.async.cg.shared.global [%0], [%1], 16;\n" :: "r"(saddr), "l"(g));
}
__device__ __forceinline__ void cp_commit() {
    asm volatile("cp.async.commit_group;\n" ::: "memory");
}
__device__ __forceinline__ void cp_wait0() {
    asm volatile("cp.async.wait_group 0;\n" ::: "memory");
}
__device__ __forceinline__ void cp_wait1() {
    asm volatile("cp.async.wait_group 1;\n" ::: "memory");
}
// copy one 32KB packed weight matrix with 128 threads (16 x 16B per thread)
__device__ __forceinline__ void issue_w(uint32_t sdst, const char* gsrc, int gt) {
#pragma unroll
    for (int i = 0; i < 16; i++) {
        int b = (gt + i * GT) * 16;
        cp16(sdst + b, gsrc + b);
    }
    cp_commit();
}

// ---------------- setup: pack weights, head collapse, zero out ----------------
__global__ void nam_setup(float* __restrict__ out, int n_out,
                          const float* __restrict__ W2, const float* __restrict__ W3,
                          const float* __restrict__ W4,
                          const float* __restrict__ Wh1, const float* __restrict__ bh1,
                          const float* __restrict__ Wh2, const float* __restrict__ bh2) {
    const int blk = blockIdx.x;
    const int tid = threadIdx.x;
    if (blk < 3 * F_SZ) {
        const int l = blk / F_SZ, f = blk % F_SZ;
        const float* W = (l == 0 ? W2 : (l == 1 ? W3 : W4)) + (long)f * H_SZ * H_SZ;
        uint32_t* hi = &g_wp[l][f][0];
        for (int e = tid; e < 4096; e += THREADS) {
            const int lane = e & 31;
            const int t = lane & 3, g = lane >> 2;
            const int nt = (e >> 5) & 15, ks = e >> 9;
            const int n = nt * 8 + g;
            const int k0 = ks * 16 + t * 2;
            float w00 = W[(k0)     * H_SZ + n];
            float w01 = W[(k0 + 1) * H_SZ + n];
            float w10 = W[(k0 + 8) * H_SZ + n];
            float w11 = W[(k0 + 9) * H_SZ + n];
            hi[2 * e]     = pack2h(w00, w01);
            hi[2 * e + 1] = pack2h(w10, w11);
        }
    } else if (blk < 3 * F_SZ + F_SZ * T_SZ) {
        const int ft = blk - 3 * F_SZ;
        __shared__ float s2[H2_SZ];
        if (tid < H2_SZ) s2[tid] = Wh2[ft * H2_SZ + tid];
        __syncthreads();
        if (tid < H_SZ) {
            const float* wp = Wh1 + ((long)ft * H_SZ + tid) * H2_SZ;
            float s = 0.0f;
#pragma unroll 8
            for (int m = 0; m < H2_SZ; m++) s += wp[m] * s2[m];
            g_wv[ft * H_SZ + tid] = s;
            if (tid == 0) {
                float cc = bh2[ft];
                const float* bp = bh1 + ft * H2_SZ;
                for (int m = 0; m < H2_SZ; m++) cc += bp[m] * s2[m];
                g_c[ft] = cc;
            }
        }
    } else {
        int i = (blk - (3 * F_SZ + F_SZ * T_SZ)) * THREADS + tid;
        if (i < n_out) out[i] = 0.0f;
    }
}

// ---------------- fused main kernel ----------------
// smem: [0,32K) g0 buf0, [32K,64K) g0 buf1, [64K,96K) g1 buf0, [96K,128K) g1 buf1
#define FS_OFF  131072
#define GF      1024     // floats of small area per group
#define SX_I    0        // 64
#define SW1_I   64       // 128
#define SB1_I   192      // 128
#define SBIAS_I 320      // 384 (b2|b3|b4)
#define SWV_I   704      // 256
#define SC_I    960      // 2
#define SMEM_BYTES (FS_OFF + 2 * GF * 4)

#define GBAR() asm volatile("bar.sync %0, 128;" :: "r"(gid + 1) : "memory")

__global__ void __launch_bounds__(THREADS, 1)
nam_main(const float* __restrict__ x, const int* __restrict__ a,
         const float* __restrict__ W1, const float* __restrict__ b1,
         const float* __restrict__ b2, const float* __restrict__ b3,
         const float* __restrict__ b4, float* __restrict__ out) {
    extern __shared__ char smem[];

    const int tid = threadIdx.x;
    const int gid = tid >> 7;        // group 0/1
    const int gt  = tid & 127;       // thread within group
    const int w4 = gt >> 5, lane = gt & 31;
    const int t = lane & 3, g = lane >> 2;
    const int t2 = t * 2;
    const int lr0 = 16 * w4 + g;     // local row (acc c0/c1), 0..63
    const int lr1 = lr0 + 8;
    const int b0 = blockIdx.x * TB;
    const int fbase = blockIdx.y * (2 * FG) + gid * FG;
    const int grow0 = b0 + lr0, grow1 = b0 + lr1;

    float* fs  = (float*)(smem + FS_OFF) + gid * GF;
    float* sx    = fs + SX_I;
    float* sw1   = fs + SW1_I;
    float* sb1   = fs + SB1_I;
    float* sbias = fs + SBIAS_I;
    float* swv   = fs + SWV_I;
    float* sc    = fs + SC_I;

    const uint32_t smem_u32 = (uint32_t)__cvta_generic_to_shared(smem);
    const uint32_t wgbase = smem_u32 + (uint32_t)gid * 65536u;
    const char* const wgen = smem + gid * 65536;

    const int t0 = a[grow0], t1 = a[grow1];
    const int t0w = t0 * H_SZ, t1w = t1 * H_SZ;

    float acc[16][4];
    uint32_t Ah[8][4], Al[8][4];
    float bbs[16][4];
#pragma unroll
    for (int nt = 0; nt < 16; nt++)
#pragma unroll
        for (int j = 0; j < 4; j++) bbs[nt][j] = 0.0f;
    float yacc0 = 0.0f, yacc1 = 0.0f;

    // prologue: steps 0 and 1 (feature fbase, layers W2 and W3)
    issue_w(wgbase,          (const char*)&g_wp[0][fbase][0], gt);
    issue_w(wgbase + 32768u, (const char*)&g_wp[1][fbase][0], gt);

    // anti-phase skew: group 1 starts ~half a layer period late so its
    // tensor phases overlap group 0's alu phases (loads already in flight)
    if (gid == 1) {
        long long s = clock64();
        while (clock64() - s < SKEW_CYC) {}
    }

    for (int ff = 0; ff < FG; ff++) {
        const int f = fbase + ff;
        GBAR();   // prev feature consumers done with small buffers
        if (gt < TB) sx[gt] = x[(long)(b0 + gt) * F_SZ + f];
        sw1[gt]         = W1[f * H_SZ + gt];
        sb1[gt]         = b1[f * H_SZ + gt];
        sbias[gt]       = b2[f * H_SZ + gt];
        sbias[128 + gt] = b3[f * H_SZ + gt];
        sbias[256 + gt] = b4[f * H_SZ + gt];
        swv[gt]       = g_wv[f * 256 + gt];
        swv[128 + gt] = g_wv[f * 256 + 128 + gt];
        if (gt < 2) sc[gt] = g_c[f * 2 + gt];
        GBAR();

        // ---- layer 1: build A-fragments directly (hi/lo fp16 split) ----
        {
            const float xv0 = sx[lr0], xv1 = sx[lr1];
#pragma unroll
            for (int kk = 0; kk < 8; kk++) {
                const int cA = 16 * kk + t2, cB = cA + 8;
                float2 wA = *(const float2*)&sw1[cA];
                float2 bA = *(const float2*)&sb1[cA];
                float2 wB = *(const float2*)&sw1[cB];
                float2 bB = *(const float2*)&sb1[cB];
                float r0, r1;
                float v0 = elu_f(xv0 * wA.x + bA.x);
                float v1 = elu_f(xv0 * wA.y + bA.y);
                Ah[kk][0] = pack_split(v0, v1, r0, r1); Al[kk][0] = pack2h(r0, r1);
                v0 = elu_f(xv1 * wA.x + bA.x);
                v1 = elu_f(xv1 * wA.y + bA.y);
                Ah[kk][1] = pack_split(v0, v1, r0, r1); Al[kk][1] = pack2h(r0, r1);
                v0 = elu_f(xv0 * wB.x + bB.x);
                v1 = elu_f(xv0 * wB.y + bB.y);
                Ah[kk][2] = pack_split(v0, v1, r0, r1); Al[kk][2] = pack2h(r0, r1);
                v0 = elu_f(xv1 * wB.x + bB.x);
                v1 = elu_f(xv1 * wB.y + bB.y);
                Ah[kk][3] = pack_split(v0, v1, r0, r1); Al[kk][3] = pack2h(r0, r1);
            }
        }

#pragma unroll 1
        for (int l = 0; l < 3; l++) {
            const int step = ff * 3 + l;
            if (step == NSTEP - 1) cp_wait0(); else cp_wait1();
            GBAR();   // this step's weight buffer ready & visible to group

            const uint32_t* Wh =
                (const uint32_t*)(wgen + (step & 1) * 32768);

            // ---- 2-pass split GEMM (Ah*Wh + Al*Wh), shared B fragments ----
#pragma unroll
            for (int nt = 0; nt < 16; nt++) {
                acc[nt][0] = 0.f; acc[nt][1] = 0.f;
                acc[nt][2] = 0.f; acc[nt][3] = 0.f;
            }
#pragma unroll
            for (int ks = 0; ks < 8; ks++) {
                const uint32_t* bh = Wh + ks * 1024 + lane * 2;
#pragma unroll
                for (int nt = 0; nt < 16; nt++) {
                    uint2 wh = *(const uint2*)(bh + nt * 64);
                    mma16816(acc[nt], Ah[ks], wh.x, wh.y);
                    mma16816(acc[nt], Al[ks], wh.x, wh.y);
                }
            }

            GBAR();   // all group threads done reading this weight buffer

            // prefetch step+2 into the buffer just released
            const int s2 = step + 2;
            if (s2 < NSTEP)
                issue_w(wgbase + (uint32_t)(step & 1) * 32768u,
                        (const char*)&g_wp[s2 % 3][fbase + s2 / 3][0], gt);

            if (l < 2) {
                // ---- epilogue: bias + ELU + split -> next layer's A frags ----
                const float* sb = sbias + l * 128;
#pragma unroll
                for (int kk = 0; kk < 8; kk++) {
                    const int nt0 = 2 * kk, nt1 = 2 * kk + 1;
                    float2 bA = *(const float2*)&sb[8 * nt0 + t2];
                    float2 bB = *(const float2*)&sb[8 * nt1 + t2];
                    float r0, r1;
                    float v0 = elu_f(acc[nt0][0] + bA.x);
                    float v1 = elu_f(acc[nt0][1] + bA.y);
                    Ah[kk][0] = pack_split(v0, v1, r0, r1); Al[kk][0] = pack2h(r0, r1);
                    v0 = elu_f(acc[nt0][2] + bA.x);
                    v1 = elu_f(acc[nt0][3] + bA.y);
                    Ah[kk][1] = pack_split(v0, v1, r0, r1); Al[kk][1] = pack2h(r0, r1);
                    v0 = elu_f(acc[nt1][0] + bB.x);
                    v1 = elu_f(acc[nt1][1] + bB.y);
                    Ah[kk][2] = pack_split(v0, v1, r0, r1); Al[kk][2] = pack2h(r0, r1);
                    v0 = elu_f(acc[nt1][2] + bB.x);
                    v1 = elu_f(acc[nt1][3] + bB.y);
                    Ah[kk][3] = pack_split(v0, v1, r0, r1); Al[kk][3] = pack2h(r0, r1);
                }
            } else {
                // ---- layer-4 epilogue: bb accumulate + collapsed head ----
                const float* sb4 = sbias + 256;
                float y0 = 0.0f, y1 = 0.0f;
#pragma unroll
                for (int nt = 0; nt < 16; nt++) {
                    float2 b4v = *(const float2*)&sb4[8 * nt + t2];
                    float bb0 = acc[nt][0] + b4v.x;
                    float bb1 = acc[nt][1] + b4v.y;
                    float bb2 = acc[nt][2] + b4v.x;
                    float bb3 = acc[nt][3] + b4v.y;
                    bbs[nt][0] += bb0; bbs[nt][1] += bb1;
                    bbs[nt][2] += bb2; bbs[nt][3] += bb3;
                    float2 wv0 = *(const float2*)&swv[t0w + 8 * nt + t2];
                    float2 wv1 = *(const float2*)&swv[t1w + 8 * nt + t2];
                    y0 += bb0 * wv0.x + bb1 * wv0.y;
                    y1 += bb2 * wv1.x + bb3 * wv1.y;
                }
                if (t == 0) { y0 += sc[t0]; y1 += sc[t1]; }
                yacc0 += y0; yacc1 += y1;
            }
        }
    }

    // ---- finale: atomics into output ----
#pragma unroll
    for (int nt = 0; nt < 16; nt++) {
        const int col = 8 * nt + t2;
        atomicAdd(&out[(long)grow0 * H_SZ + col],     bbs[nt][0]);
        atomicAdd(&out[(long)grow0 * H_SZ + col + 1], bbs[nt][1]);
        atomicAdd(&out[(long)grow1 * H_SZ + col],     bbs[nt][2]);
        atomicAdd(&out[(long)grow1 * H_SZ + col + 1], bbs[nt][3]);
    }
    yacc0 += __shfl_xor_sync(0xffffffffu, yacc0, 1);
    yacc0 += __shfl_xor_sync(0xffffffffu, yacc0, 2);
    yacc1 += __shfl_xor_sync(0xffffffffu, yacc1, 1);
    yacc1 += __shfl_xor_sync(0xffffffffu, yacc1, 2);
    if (t == 0) {
        atomicAdd(&out[B_SZ * H_SZ + grow0], yacc0);
        atomicAdd(&out[B_SZ * H_SZ + grow1], yacc1);
    }
}

// ---------------- launch ----------------
extern "C" void kernel_launch(void* const* d_in, const int* in_sizes, int n_in,
                              void* d_out, int out_size) {
    const float* x   = (const float*)d_in[0];
    const int*   a   = (const int*)d_in[1];
    const float* W1  = (const float*)d_in[2];
    const float* b1  = (const float*)d_in[3];
    const float* W2  = (const float*)d_in[4];
    const float* b2  = (const float*)d_in[5];
    const float* W3  = (const float*)d_in[6];
    const float* b3  = (const float*)d_in[7];
    const float* W4  = (const float*)d_in[8];
    const float* b4  = (const float*)d_in[9];
    const float* Wh1 = (const float*)d_in[10];
    const float* bh1 = (const float*)d_in[11];
    const float* Wh2 = (const float*)d_in[12];
    const float* bh2 = (const float*)d_in[13];
    float* out = (float*)d_out;

    cudaFuncSetAttribute(nam_main, cudaFuncAttributeMaxDynamicSharedMemorySize,
                         SMEM_BYTES);

    const int zero_blocks = (out_size + THREADS - 1) / THREADS;
    nam_setup<<<3 * F_SZ + F_SZ * T_SZ + zero_blocks, THREADS>>>(
        out, out_size, W2, W3, W4, Wh1, bh1, Wh2, bh2);

    dim3 grid(B_SZ / TB, F_SZ / (2 * FG));
    nam_main<<<grid, THREADS, SMEM_BYTES>>>(x, a, W1, b1, b2, b3, b4, out);
}